// round 1
// baseline (speedup 1.0000x reference)
#include <cuda_runtime.h>

#define B 64
#define S 128
#define E 512
#define H 512
#define A 256
#define V 8192
#define T 32
#define HE 1024   /* H + E */
#define G4 2048   /* 4*H   */

typedef unsigned long long ull;

// ---------------- persistent device scratch (no allocations allowed) -------
__device__ float g_enc_proj[B * S * A];   // 8 MB
__device__ float g_xemb[T * B * H];       // 4 MB (all-step embedding gather)
__device__ float g_scores[B * S];
__device__ float g_h[B * H];
__device__ float g_c[B * H];
__device__ float g_xcat[B * HE];          // [x_emb | ctx]
__device__ float g_hctx[B * HE];          // [h_new | ctx]
__device__ float g_gates[B * G4];
__device__ float g_bias[G4];              // b_ih + b_hh

// ---------------- helpers --------------------------------------------------
__device__ __forceinline__ float fast_tanh(float x) {
    float r; asm("tanh.approx.f32 %0, %1;" : "=f"(r) : "f"(x)); return r;
}
// Blackwell packed fp32 FMA (2 FMAs / instr). ptxas never auto-emits this.
__device__ __forceinline__ void ffma2(ull& d, ull a, ull b) {
    asm("fma.rn.f32x2 %0, %1, %2, %0;" : "+l"(d) : "l"(a), "l"(b));
}
__device__ __forceinline__ float unpack_sum(ull a) {
    float lo = __uint_as_float((unsigned)(a & 0xffffffffull));
    float hi = __uint_as_float((unsigned)(a >> 32));
    return lo + hi;
}

// ---------------- init: h=c=0, fused LSTM bias -----------------------------
__global__ void k_init(const float* __restrict__ b_ih, const float* __restrict__ b_hh) {
    int idx = blockIdx.x * 256 + threadIdx.x;
    if (idx < B * H) { g_h[idx] = 0.f; g_c[idx] = 0.f; }
    if (idx < G4) g_bias[idx] = b_ih[idx] + b_hh[idx];
}

// ---------------- gather teacher-forced embeddings for ALL steps -----------
__global__ void k_embed(const int* __restrict__ tgt, const float* __restrict__ emb) {
    int idx = blockIdx.x * 256 + threadIdx.x;   // T*B*H = 1M
    int hh = idx & (H - 1);
    int rb = idx >> 9;          // t*B + b
    int b  = rb & (B - 1);
    int t  = rb >> 6;
    int tok = (t == 0) ? 0 : tgt[b * T + (t - 1)];
    g_xemb[idx] = emb[tok * H + hh];
}

// ---------------- enc_proj = enc[8192,512] @ W_enc[512,256] ----------------
// 64x64x32 tile, k-major smem (pad 34), f32x2 packed along K.
__global__ void __launch_bounds__(256) k_encproj(const float* __restrict__ Aenc,
                                                 const float* __restrict__ Wenc) {
    __shared__ __align__(16) float As[64 * 34];
    __shared__ __align__(16) float Bs[64 * 34];
    int t = threadIdx.x;
    int n0 = blockIdx.x * 64, m0 = blockIdx.y * 64;
    int tn = t & 15, tm = t >> 4;
    ull acc[4][4];
#pragma unroll
    for (int i = 0; i < 4; i++)
#pragma unroll
        for (int j = 0; j < 4; j++) acc[i][j] = 0ull;

    for (int k0 = 0; k0 < E; k0 += 32) {
        {   // A tile [64m][32k], coalesced on k
            int kk = t & 31, mb = t >> 5;
#pragma unroll
            for (int i = 0; i < 8; i++)
                As[(mb + 8 * i) * 34 + kk] = Aenc[(m0 + mb + 8 * i) * E + k0 + kk];
        }
        {   // B tile: W_enc is k-strided, coalesce on n
            int nn = t & 63, kb = t >> 6;
#pragma unroll
            for (int i = 0; i < 8; i++)
                Bs[nn * 34 + kb + 4 * i] = Wenc[(k0 + kb + 4 * i) * A + n0 + nn];
        }
        __syncthreads();
#pragma unroll
        for (int kp = 0; kp < 16; kp++) {
            ull xa[4], wb[4];
#pragma unroll
            for (int i = 0; i < 4; i++) xa[i] = *(const ull*)&As[(tm + 16 * i) * 34 + 2 * kp];
#pragma unroll
            for (int j = 0; j < 4; j++) wb[j] = *(const ull*)&Bs[(tn + 16 * j) * 34 + 2 * kp];
#pragma unroll
            for (int i = 0; i < 4; i++)
#pragma unroll
                for (int j = 0; j < 4; j++) ffma2(acc[i][j], xa[i], wb[j]);
        }
        __syncthreads();
    }
#pragma unroll
    for (int i = 0; i < 4; i++)
#pragma unroll
        for (int j = 0; j < 4; j++) {
            int m = m0 + tm + 16 * i, n = n0 + tn + 16 * j;
            g_enc_proj[m * A + n] = unpack_sum(acc[i][j]);
        }
}

// ---------------- per-step: dec proj + tanh + scores; also zero gates ------
__global__ void k_attn(const float* __restrict__ Wdec,
                       const float* __restrict__ b_att,
                       const float* __restrict__ v_att) {
    int b = blockIdx.x, t = threadIdx.x;
    __shared__ float sh_h[H];
    __shared__ float sh_dec[A];
    __shared__ float sh_v[A];
    sh_h[t]       = g_h[b * H + t];
    sh_h[t + 256] = g_h[b * H + t + 256];
    if (t < A) sh_v[t] = v_att[t];
#pragma unroll
    for (int k = 0; k < 8; k++) g_gates[b * G4 + t + 256 * k] = 0.f;  // for split-K atomics
    __syncthreads();

    if (t < 128) {                       // dec[a] = h . W_dec[:,a] + b_att
        int a0 = 2 * t;
        float2 d = *(const float2*)&b_att[a0];
#pragma unroll 8
        for (int hh = 0; hh < H; hh++) {
            float hv = sh_h[hh];
            float2 w = *(const float2*)&Wdec[hh * A + a0];
            d.x += hv * w.x; d.y += hv * w.y;
        }
        sh_dec[a0] = d.x; sh_dec[a0 + 1] = d.y;
    }
    __syncthreads();

    int wid = t >> 5, lane = t & 31;
    for (int s = wid; s < S; s += 8) {
        const float* ep = &g_enc_proj[(b * S + s) * A];
        float p = 0.f;
#pragma unroll
        for (int q = 0; q < 8; q++) {
            int a = lane + 32 * q;
            p += fast_tanh(ep[a] + sh_dec[a]) * sh_v[a];
        }
#pragma unroll
        for (int off = 16; off; off >>= 1) p += __shfl_down_sync(0xffffffffu, p, off);
        if (lane == 0) g_scores[b * S + s] = p;
    }
}

// ---------------- per-step: softmax + context + assemble xcat --------------
__global__ void k_softctx(const float* __restrict__ enc, int step) {
    int b = blockIdx.x, tid = threadIdx.x;
    __shared__ float sw[S];
    __shared__ float sred;
    if (tid < S) sw[tid] = g_scores[b * S + tid];
    __syncthreads();
    if (tid < 32) {
        float m = fmaxf(fmaxf(sw[tid], sw[tid + 32]), fmaxf(sw[tid + 64], sw[tid + 96]));
#pragma unroll
        for (int off = 16; off; off >>= 1) m = fmaxf(m, __shfl_xor_sync(0xffffffffu, m, off));
        if (tid == 0) sred = m;
    }
    __syncthreads();
    float mx = sred;
    if (tid < S) sw[tid] = expf(sw[tid] - mx);
    __syncthreads();
    if (tid < 32) {
        float ssum = sw[tid] + sw[tid + 32] + sw[tid + 64] + sw[tid + 96];
#pragma unroll
        for (int off = 16; off; off >>= 1) ssum += __shfl_xor_sync(0xffffffffu, ssum, off);
        if (tid == 0) sred = 1.f / ssum;
    }
    __syncthreads();
    float rinv = sred;

    // ctx[e] = sum_s w[s]*enc[b,s,e]   (two consecutive e per thread)
    int c = 2 * tid;
    float2 acc = make_float2(0.f, 0.f);
    const float* eb = &enc[b * S * E];
#pragma unroll 4
    for (int s = 0; s < S; s++) {
        float ws = sw[s];
        float2 ev = *(const float2*)&eb[s * E + c];
        acc.x += ws * ev.x; acc.y += ws * ev.y;
    }
    acc.x *= rinv; acc.y *= rinv;
    g_xcat[b * HE + H + c] = acc.x;  g_xcat[b * HE + H + c + 1] = acc.y;
    g_hctx[b * HE + H + c] = acc.x;  g_hctx[b * HE + H + c + 1] = acc.y;

    // x_emb -> xcat[:, :H]
    g_xcat[b * HE + tid]       = g_xemb[(step * B + b) * H + tid];
    g_xcat[b * HE + tid + 256] = g_xemb[(step * B + b) * H + tid + 256];
}

// ---------------- generic M=64 GEMM: C[64,N] = X1@W1^T (+ X2@W2^T) ---------
// BN=64, BK=32, 4x4 microtile, f32x2 packed along K; optional split-K (atomics).
__global__ void __launch_bounds__(256) k_gemm(
    const float* __restrict__ X1, int ld1, int nc1,
    const float* __restrict__ W1, int lw1,
    const float* __restrict__ X2, int ld2, int nc2,
    const float* __restrict__ W2, int lw2,
    float* __restrict__ C, int ldc, int nsplit,
    const float* __restrict__ bias)
{
    __shared__ __align__(16) float Xs[64 * 34];
    __shared__ __align__(16) float Ws[64 * 34];
    int t = threadIdx.x;
    int n0 = blockIdx.x * 64;
    int tn = t & 15, tm = t >> 4;
    ull acc[4][4];
#pragma unroll
    for (int i = 0; i < 4; i++)
#pragma unroll
        for (int j = 0; j < 4; j++) acc[i][j] = 0ull;

    int total = nc1 + nc2;
    int kk = t & 31, rb = t >> 5;
    for (int cch = blockIdx.y; cch < total; cch += nsplit) {
        const float *X, *W; int ldx, ldw, k0;
        if (cch < nc1) { X = X1; W = W1; ldx = ld1; ldw = lw1; k0 = cch * 32; }
        else           { X = X2; W = W2; ldx = ld2; ldw = lw2; k0 = (cch - nc1) * 32; }
#pragma unroll
        for (int i = 0; i < 8; i++)
            Xs[(rb + 8 * i) * 34 + kk] = X[(rb + 8 * i) * ldx + k0 + kk];
#pragma unroll
        for (int i = 0; i < 8; i++)
            Ws[(rb + 8 * i) * 34 + kk] = W[(n0 + rb + 8 * i) * ldw + k0 + kk];
        __syncthreads();
#pragma unroll
        for (int kp = 0; kp < 16; kp++) {
            ull xa[4], wb[4];
#pragma unroll
            for (int i = 0; i < 4; i++) xa[i] = *(const ull*)&Xs[(tm + 16 * i) * 34 + 2 * kp];
#pragma unroll
            for (int j = 0; j < 4; j++) wb[j] = *(const ull*)&Ws[(tn + 16 * j) * 34 + 2 * kp];
#pragma unroll
            for (int i = 0; i < 4; i++)
#pragma unroll
                for (int j = 0; j < 4; j++) ffma2(acc[i][j], xa[i], wb[j]);
        }
        __syncthreads();
    }
#pragma unroll
    for (int i = 0; i < 4; i++)
#pragma unroll
        for (int j = 0; j < 4; j++) {
            int m = tm + 16 * i, n = n0 + tn + 16 * j;
            float v = unpack_sum(acc[i][j]);
            if (nsplit > 1) atomicAdd(&C[m * ldc + n], v);
            else            C[m * ldc + n] = v + (bias ? bias[n] : 0.f);
        }
}

// ---------------- per-step: LSTM cell update -------------------------------
__global__ void k_lstm() {
    int idx = blockIdx.x * 256 + threadIdx.x;   // B*H = 32768
    int b = idx >> 9, j = idx & 511;
    const float* gr = &g_gates[b * G4];
    float gi = gr[j]         + g_bias[j];
    float gf = gr[j + 512]   + g_bias[j + 512];
    float gg = gr[j + 1024]  + g_bias[j + 1024];
    float go = gr[j + 1536]  + g_bias[j + 1536];
    float si = 1.f / (1.f + expf(-gi));
    float sf = 1.f / (1.f + expf(-gf));
    float so = 1.f / (1.f + expf(-go));
    float c  = sf * g_c[idx] + si * tanhf(gg);
    float hn = so * tanhf(c);
    g_c[idx] = c;
    g_h[idx] = hn;
    g_hctx[b * HE + j] = hn;
}

// ---------------- launch ----------------------------------------------------
extern "C" void kernel_launch(void* const* d_in, const int* in_sizes, int n_in,
                              void* d_out, int out_size) {
    const float* enc  = (const float*)d_in[0];
    const int*   tgt  = (const int*)  d_in[1];
    const float* emb  = (const float*)d_in[2];
    const float* Wenc = (const float*)d_in[3];
    const float* Wdec = (const float*)d_in[4];
    const float* batt = (const float*)d_in[5];
    const float* vatt = (const float*)d_in[6];
    const float* Wih  = (const float*)d_in[7];
    const float* Whh  = (const float*)d_in[8];
    const float* bih  = (const float*)d_in[9];
    const float* bhh  = (const float*)d_in[10];
    const float* Wout = (const float*)d_in[11];
    const float* bout = (const float*)d_in[12];
    float* out = (float*)d_out;

    float *xcat, *hctx, *gates, *hbuf;
    cudaGetSymbolAddress((void**)&xcat,  g_xcat);
    cudaGetSymbolAddress((void**)&hctx,  g_hctx);
    cudaGetSymbolAddress((void**)&gates, g_gates);
    cudaGetSymbolAddress((void**)&hbuf,  g_h);

    k_init<<<128, 256>>>(bih, bhh);
    k_embed<<<(T * B * H) / 256, 256>>>(tgt, emb);
    k_encproj<<<dim3(A / 64, (B * S) / 64), 256>>>(enc, Wenc);

    for (int t = 0; t < T; t++) {
        k_attn<<<B, 256>>>(Wdec, batt, vatt);
        k_softctx<<<B, 256>>>(enc, t);
        // gates = xcat@W_ih^T + h@W_hh^T  (split-K=4, atomics; bias added in LSTM)
        k_gemm<<<dim3(G4 / 64, 4), 256>>>(xcat, HE, HE / 32, Wih, HE,
                                          hbuf, H,  H / 32,  Whh, H,
                                          gates, G4, 4, nullptr);
        k_lstm<<<(B * H) / 256, 256>>>();
        // out[:, t, :] = hctx@W_out^T + b_out   (128 blocks, direct store)
        k_gemm<<<dim3(V / 64, 1), 256>>>(hctx, HE, HE / 32, Wout, HE,
                                         nullptr, 0, 0, nullptr, 0,
                                         out + t * V, T * V, 1, bout);
    }
}

// round 2
// speedup vs baseline: 1.5694x; 1.5694x over previous
#include <cuda_runtime.h>

#define B 64
#define S 128
#define E 512
#define H 512
#define A 256
#define V 8192
#define T 32
#define HE 1024   /* H + E */
#define G4 2048   /* 4*H   */

typedef unsigned long long ull;

// ---------------- persistent device scratch (no allocations allowed) -------
__device__ float g_enc_proj[B * S * A];   // 8 MB
__device__ float g_xemb[T * B * H];       // 4 MB
__device__ float g_dec[B * A];
__device__ float g_scores[B * S];
__device__ float g_h[B * H];
__device__ float g_c[B * H];
__device__ float g_xcat[B * HE];          // [x_emb | ctx]
__device__ float g_hctx[B * HE];          // [h_new | ctx]
__device__ float g_gates[B * G4];
__device__ float g_bias[G4];              // b_ih + b_hh

// ---------------- helpers --------------------------------------------------
__device__ __forceinline__ float fast_tanh(float x) {
    float r; asm("tanh.approx.f32 %0, %1;" : "=f"(r) : "f"(x)); return r;
}
__device__ __forceinline__ void ffma2(ull& d, ull a, ull b) {
    asm("fma.rn.f32x2 %0, %1, %2, %0;" : "+l"(d) : "l"(a), "l"(b));
}
__device__ __forceinline__ float unpack_sum(ull a) {
    float lo = __uint_as_float((unsigned)(a & 0xffffffffull));
    float hi = __uint_as_float((unsigned)(a >> 32));
    return lo + hi;
}

// ---------------- init: h=c=0, fused LSTM bias -----------------------------
__global__ void k_init(const float* __restrict__ b_ih, const float* __restrict__ b_hh) {
    int idx = blockIdx.x * 256 + threadIdx.x;
    if (idx < B * H) { g_h[idx] = 0.f; g_c[idx] = 0.f; }
    if (idx < G4) g_bias[idx] = b_ih[idx] + b_hh[idx];
}

// ---------------- gather teacher-forced embeddings for ALL steps -----------
__global__ void k_embed(const int* __restrict__ tgt, const float* __restrict__ emb) {
    int idx = blockIdx.x * 256 + threadIdx.x;   // T*B*H = 1M
    int hh = idx & (H - 1);
    int rb = idx >> 9;          // t*B + b
    int b  = rb & (B - 1);
    int t  = rb >> 6;
    int tok = (t == 0) ? 0 : tgt[b * T + (t - 1)];
    g_xemb[idx] = emb[tok * H + hh];
}

// ---------------- enc_proj = enc[8192,512] @ W_enc[512,256] ----------------
__global__ void __launch_bounds__(256) k_encproj(const float* __restrict__ Aenc,
                                                 const float* __restrict__ Wenc) {
    __shared__ __align__(16) float As[64 * 34];
    __shared__ __align__(16) float Bs[64 * 34];
    int t = threadIdx.x;
    int n0 = blockIdx.x * 64, m0 = blockIdx.y * 64;
    int tn = t & 15, tm = t >> 4;
    ull acc[4][4];
#pragma unroll
    for (int i = 0; i < 4; i++)
#pragma unroll
        for (int j = 0; j < 4; j++) acc[i][j] = 0ull;

    for (int k0 = 0; k0 < E; k0 += 32) {
        {
            int kk = t & 31, mb = t >> 5;
#pragma unroll
            for (int i = 0; i < 8; i++)
                As[(mb + 8 * i) * 34 + kk] = Aenc[(m0 + mb + 8 * i) * E + k0 + kk];
        }
        {
            int nn = t & 63, kb = t >> 6;
#pragma unroll
            for (int i = 0; i < 8; i++)
                Bs[nn * 34 + kb + 4 * i] = Wenc[(k0 + kb + 4 * i) * A + n0 + nn];
        }
        __syncthreads();
#pragma unroll
        for (int kp = 0; kp < 16; kp++) {
            ull xa[4], wb[4];
#pragma unroll
            for (int i = 0; i < 4; i++) xa[i] = *(const ull*)&As[(tm + 16 * i) * 34 + 2 * kp];
#pragma unroll
            for (int j = 0; j < 4; j++) wb[j] = *(const ull*)&Bs[(tn + 16 * j) * 34 + 2 * kp];
#pragma unroll
            for (int i = 0; i < 4; i++)
#pragma unroll
                for (int j = 0; j < 4; j++) ffma2(acc[i][j], xa[i], wb[j]);
        }
        __syncthreads();
    }
#pragma unroll
    for (int i = 0; i < 4; i++)
#pragma unroll
        for (int j = 0; j < 4; j++) {
            int m = m0 + tm + 16 * i, n = n0 + tn + 16 * j;
            g_enc_proj[m * A + n] = unpack_sum(acc[i][j]);
        }
}

// ---------------- per-step: dec[b,a] = h.W_dec + b_att; zero gates ---------
// grid (B, 2): a-half per block; 2 threads per a (k halves) + shared reduce.
__global__ void __launch_bounds__(256) k_decproj(const float* __restrict__ Wdec,
                                                 const float* __restrict__ b_att) {
    __shared__ float sh_h[H];
    __shared__ float sred[256];
    int b = blockIdx.x, half = blockIdx.y, tid = threadIdx.x;
    sh_h[tid]       = g_h[b * H + tid];
    sh_h[tid + 256] = g_h[b * H + tid + 256];
    // zero gates for split-K atomics (128 blocks x 256 thr x 4 = 131072)
    {
        int gi = ((b * 2 + half) * 256 + tid) * 4;
        *(float4*)&g_gates[gi] = make_float4(0.f, 0.f, 0.f, 0.f);
    }
    __syncthreads();

    int a = half * 128 + (tid & 127);
    int kh = tid >> 7;                 // 0 or 1
    float acc = 0.f;
    const float* wp = &Wdec[kh * 256 * A + a];
#pragma unroll 8
    for (int k = 0; k < 256; k++)
        acc += sh_h[kh * 256 + k] * wp[k * A];
    sred[tid] = acc;
    __syncthreads();
    if (tid < 128)
        g_dec[b * A + half * 128 + tid] = sred[tid] + sred[tid + 128] + b_att[a];
}

// ---------------- per-step: scores + seed out slice with bias --------------
// grid (B, 8 s-chunks); each warp does 2 s-rows.
__global__ void __launch_bounds__(256) k_score(const float* __restrict__ v_att,
                                               const float* __restrict__ bout,
                                               float* __restrict__ out, int step) {
    __shared__ float sh_dec[A];
    __shared__ float sh_v[A];
    int b = blockIdx.x, sc = blockIdx.y, tid = threadIdx.x;
    sh_dec[tid] = g_dec[b * A + tid];
    sh_v[tid]   = v_att[tid];
    // seed out[b, step, :] with bias (before out-GEMM atomics)
    {
        int n = sc * 1024 + tid * 4;
        *(float4*)&out[(b * T + step) * V + n] = *(const float4*)&bout[n];
    }
    __syncthreads();

    int wid = tid >> 5, lane = tid & 31;
#pragma unroll
    for (int r = 0; r < 2; r++) {
        int s = sc * 16 + wid * 2 + r;
        const float* ep = &g_enc_proj[(b * S + s) * A];
        float p = 0.f;
#pragma unroll
        for (int q = 0; q < 8; q++) {
            int a = lane + 32 * q;
            p += fast_tanh(ep[a] + sh_dec[a]) * sh_v[a];
        }
#pragma unroll
        for (int off = 16; off; off >>= 1) p += __shfl_down_sync(0xffffffffu, p, off);
        if (lane == 0) g_scores[b * S + s] = p;
    }
}

// ---------------- per-step: softmax + context + assemble xcat --------------
// grid (B, 4 e-chunks); softmax recomputed per block (cheap); s split in halves.
__global__ void __launch_bounds__(256) k_softctx(const float* __restrict__ enc, int step) {
    __shared__ float sw[S];
    __shared__ float sacc[256];
    __shared__ float sred;
    int b = blockIdx.x, ec = blockIdx.y, tid = threadIdx.x;
    if (tid < S) sw[tid] = g_scores[b * S + tid];
    __syncthreads();
    if (tid < 32) {
        float m = fmaxf(fmaxf(sw[tid], sw[tid + 32]), fmaxf(sw[tid + 64], sw[tid + 96]));
#pragma unroll
        for (int off = 16; off; off >>= 1) m = fmaxf(m, __shfl_xor_sync(0xffffffffu, m, off));
        if (tid == 0) sred = m;
    }
    __syncthreads();
    float mx = sred;
    if (tid < S) sw[tid] = expf(sw[tid] - mx);
    __syncthreads();
    if (tid < 32) {
        float ssum = sw[tid] + sw[tid + 32] + sw[tid + 64] + sw[tid + 96];
#pragma unroll
        for (int off = 16; off; off >>= 1) ssum += __shfl_xor_sync(0xffffffffu, ssum, off);
        if (tid == 0) sred = 1.f / ssum;
    }
    __syncthreads();
    float rinv = sred;

    // ctx[e] for e-chunk; 2 threads per e over s-halves
    int e  = ec * 128 + (tid & 127);
    int sh = tid >> 7;                // 0/1
    float acc = 0.f;
    const float* eb = &enc[b * S * E + sh * 64 * E + e];
#pragma unroll 8
    for (int s = 0; s < 64; s++)
        acc += sw[sh * 64 + s] * eb[s * E];
    sacc[tid] = acc;
    __syncthreads();
    if (tid < 128) {
        float v = (sacc[tid] + sacc[tid + 128]) * rinv;
        g_xcat[b * HE + H + ec * 128 + tid] = v;
        g_hctx[b * HE + H + ec * 128 + tid] = v;
    }
    // x_emb -> xcat[:, :H] (blocks ec 0/1 cover 512)
    if (ec < 2)
        g_xcat[b * HE + ec * 256 + tid] = g_xemb[(step * B + b) * H + ec * 256 + tid];
}

// ---------------- warp-layout GEMM: C[64,N] += X1@W1^T (+X2@W2^T) ----------
// tile 64m x 128n; warp owns 8 m-rows (X via broadcast LDS); lane owns 4 n at
// stride 32 (pad-34 rows -> conflict-free). split-K via atomics (C pre-seeded).
__global__ void __launch_bounds__(256) k_wgemm(
    const float* __restrict__ X1, int ld1, int nc1,
    const float* __restrict__ W1, int lw1,
    const float* __restrict__ X2, int ld2, int nc2,
    const float* __restrict__ W2, int lw2,
    float* __restrict__ C, int ldc, int nsplit)
{
    __shared__ __align__(16) float Xs[64 * 34];
    __shared__ __align__(16) float Ws[128 * 34];
    int t = threadIdx.x, warp = t >> 5, lane = t & 31;
    int n0 = blockIdx.x * 128;
    ull acc[8][4];
#pragma unroll
    for (int i = 0; i < 8; i++)
#pragma unroll
        for (int j = 0; j < 4; j++) acc[i][j] = 0ull;

    int kk = t & 31, r = t >> 5;
    int total = nc1 + nc2;
    for (int cch = blockIdx.y; cch < total; cch += nsplit) {
        const float *X, *W; int ldx, ldw, k0;
        if (cch < nc1) { X = X1; W = W1; ldx = ld1; ldw = lw1; k0 = cch * 32; }
        else           { X = X2; W = W2; ldx = ld2; ldw = lw2; k0 = (cch - nc1) * 32; }
#pragma unroll
        for (int i = 0; i < 8; i++)
            Xs[(r + 8 * i) * 34 + kk] = X[(r + 8 * i) * ldx + k0 + kk];
#pragma unroll
        for (int i = 0; i < 16; i++)
            Ws[(r + 8 * i) * 34 + kk] = W[(n0 + r + 8 * i) * ldw + k0 + kk];
        __syncthreads();
#pragma unroll
        for (int kp = 0; kp < 16; kp++) {
            ull xa[8], wb[4];
#pragma unroll
            for (int i = 0; i < 8; i++)
                xa[i] = *(const ull*)&Xs[(warp * 8 + i) * 34 + 2 * kp];
#pragma unroll
            for (int j = 0; j < 4; j++)
                wb[j] = *(const ull*)&Ws[(lane + 32 * j) * 34 + 2 * kp];
#pragma unroll
            for (int i = 0; i < 8; i++)
#pragma unroll
                for (int j = 0; j < 4; j++) ffma2(acc[i][j], xa[i], wb[j]);
        }
        __syncthreads();
    }
#pragma unroll
    for (int i = 0; i < 8; i++)
#pragma unroll
        for (int j = 0; j < 4; j++)
            atomicAdd(&C[(warp * 8 + i) * ldc + n0 + 32 * j + lane],
                      unpack_sum(acc[i][j]));
}

// ---------------- per-step: LSTM cell update -------------------------------
__global__ void k_lstm() {
    int idx = blockIdx.x * 256 + threadIdx.x;   // B*H = 32768
    int b = idx >> 9, j = idx & 511;
    const float* gr = &g_gates[b * G4];
    float gi = gr[j]         + g_bias[j];
    float gf = gr[j + 512]   + g_bias[j + 512];
    float gg = gr[j + 1024]  + g_bias[j + 1024];
    float go = gr[j + 1536]  + g_bias[j + 1536];
    float si = 1.f / (1.f + expf(-gi));
    float sf = 1.f / (1.f + expf(-gf));
    float so = 1.f / (1.f + expf(-go));
    float c  = sf * g_c[idx] + si * tanhf(gg);
    float hn = so * tanhf(c);
    g_c[idx] = c;
    g_h[idx] = hn;
    g_hctx[b * HE + j] = hn;
}

// ---------------- launch ----------------------------------------------------
extern "C" void kernel_launch(void* const* d_in, const int* in_sizes, int n_in,
                              void* d_out, int out_size) {
    const float* enc  = (const float*)d_in[0];
    const int*   tgt  = (const int*)  d_in[1];
    const float* emb  = (const float*)d_in[2];
    const float* Wenc = (const float*)d_in[3];
    const float* Wdec = (const float*)d_in[4];
    const float* batt = (const float*)d_in[5];
    const float* vatt = (const float*)d_in[6];
    const float* Wih  = (const float*)d_in[7];
    const float* Whh  = (const float*)d_in[8];
    const float* bih  = (const float*)d_in[9];
    const float* bhh  = (const float*)d_in[10];
    const float* Wout = (const float*)d_in[11];
    const float* bout = (const float*)d_in[12];
    float* out = (float*)d_out;

    float *xcat, *hctx, *gates, *hbuf;
    cudaGetSymbolAddress((void**)&xcat,  g_xcat);
    cudaGetSymbolAddress((void**)&hctx,  g_hctx);
    cudaGetSymbolAddress((void**)&gates, g_gates);
    cudaGetSymbolAddress((void**)&hbuf,  g_h);

    k_init<<<128, 256>>>(bih, bhh);
    k_embed<<<(T * B * H) / 256, 256>>>(tgt, emb);
    k_encproj<<<dim3(A / 64, (B * S) / 64), 256>>>(enc, Wenc);

    for (int t = 0; t < T; t++) {
        k_decproj<<<dim3(B, 2), 256>>>(Wdec, batt);
        k_score<<<dim3(B, 8), 256>>>(vatt, bout, out, t);
        k_softctx<<<dim3(B, 4), 256>>>(enc, t);
        // gates += xcat@W_ih^T + h@W_hh^T  (split-K=8; zeroed in k_decproj)
        k_wgemm<<<dim3(G4 / 128, 8), 256>>>(xcat, HE, HE / 32, Wih, HE,
                                            hbuf, H,  H / 32,  Whh, H,
                                            gates, G4, 8);
        k_lstm<<<(B * H) / 256, 256>>>();
        // out[:, t, :] += hctx@W_out^T  (split-K=2; bias seeded in k_score)
        k_wgemm<<<dim3(V / 128, 2), 256>>>(hctx, HE, HE / 32, Wout, HE,
                                           nullptr, 0, 0, nullptr, 0,
                                           out + t * V, T * V, 2);
    }
}

// round 3
// speedup vs baseline: 1.7550x; 1.1183x over previous
#include <cuda_runtime.h>

#define B 64
#define S 128
#define E 512
#define H 512
#define A 256
#define V 8192
#define T 32
#define HE 1024   /* H + E */
#define G4 2048   /* 4*H   */

typedef unsigned long long ull;

// ---------------- persistent device scratch (no allocations allowed) -------
__device__ float g_enc_proj[B * S * A];   // 8 MB
__device__ float g_xemb[T * B * H];       // 4 MB
__device__ float g_WdecT[A * H];          // transposed W_dec [A rows, H k]
__device__ float g_dec[B * A];
__device__ float g_scores[B * S];
__device__ float g_h[B * H];
__device__ float g_c[B * H];
__device__ float g_xcat[B * HE];          // [x_emb | ctx]
__device__ float g_hctx[B * HE];          // [h_new | ctx]
__device__ float g_gates[B * G4];
__device__ float g_bias[G4];              // b_ih + b_hh

// ---------------- helpers --------------------------------------------------
__device__ __forceinline__ float fast_tanh(float x) {
    float r; asm("tanh.approx.f32 %0, %1;" : "=f"(r) : "f"(x)); return r;
}
__device__ __forceinline__ void ffma2(ull& d, ull a, ull b) {
    asm("fma.rn.f32x2 %0, %1, %2, %0;" : "+l"(d) : "l"(a), "l"(b));
}
__device__ __forceinline__ float unpack_sum(ull a) {
    float lo = __uint_as_float((unsigned)(a & 0xffffffffull));
    float hi = __uint_as_float((unsigned)(a >> 32));
    return lo + hi;
}

// ---------------- init: h=c=0, fused bias, seed dec with b_att -------------
__global__ void k_init(const float* __restrict__ b_ih, const float* __restrict__ b_hh,
                       const float* __restrict__ b_att) {
    int idx = blockIdx.x * 256 + threadIdx.x;   // 32768 threads
    if (idx < B * H) { g_h[idx] = 0.f; g_c[idx] = 0.f; }
    if (idx < G4) g_bias[idx] = b_ih[idx] + b_hh[idx];
    if (idx < B * A) g_dec[idx] = b_att[idx & (A - 1)];
}

// ---------------- one-time transpose of W_dec ------------------------------
__global__ void k_transpose(const float* __restrict__ Wdec) {
    int idx = blockIdx.x * 256 + threadIdx.x;   // A*H = 131072
    int a = idx >> 9, h = idx & (H - 1);
    g_WdecT[a * H + h] = Wdec[h * A + a];
}

// ---------------- gather teacher-forced embeddings for ALL steps -----------
__global__ void k_embed(const int* __restrict__ tgt, const float* __restrict__ emb) {
    int idx = blockIdx.x * 256 + threadIdx.x;   // T*B*H = 1M
    int hh = idx & (H - 1);
    int rb = idx >> 9;          // t*B + b
    int b  = rb & (B - 1);
    int t  = rb >> 6;
    int tok = (t == 0) ? 0 : tgt[b * T + (t - 1)];
    g_xemb[idx] = emb[tok * H + hh];
}

// ---------------- enc_proj = enc[8192,512] @ W_enc[512,256] ----------------
__global__ void __launch_bounds__(256) k_encproj(const float* __restrict__ Aenc,
                                                 const float* __restrict__ Wenc) {
    __shared__ __align__(16) float As[64 * 34];
    __shared__ __align__(16) float Bs[64 * 34];
    int t = threadIdx.x;
    int n0 = blockIdx.x * 64, m0 = blockIdx.y * 64;
    int tn = t & 15, tm = t >> 4;
    ull acc[4][4];
#pragma unroll
    for (int i = 0; i < 4; i++)
#pragma unroll
        for (int j = 0; j < 4; j++) acc[i][j] = 0ull;

    for (int k0 = 0; k0 < E; k0 += 32) {
        {
            int kk = t & 31, mb = t >> 5;
#pragma unroll
            for (int i = 0; i < 8; i++)
                As[(mb + 8 * i) * 34 + kk] = Aenc[(m0 + mb + 8 * i) * E + k0 + kk];
        }
        {
            int nn = t & 63, kb = t >> 6;
#pragma unroll
            for (int i = 0; i < 8; i++)
                Bs[nn * 34 + kb + 4 * i] = Wenc[(k0 + kb + 4 * i) * A + n0 + nn];
        }
        __syncthreads();
#pragma unroll
        for (int kp = 0; kp < 16; kp++) {
            ull xa[4], wb[4];
#pragma unroll
            for (int i = 0; i < 4; i++) xa[i] = *(const ull*)&As[(tm + 16 * i) * 34 + 2 * kp];
#pragma unroll
            for (int j = 0; j < 4; j++) wb[j] = *(const ull*)&Bs[(tn + 16 * j) * 34 + 2 * kp];
#pragma unroll
            for (int i = 0; i < 4; i++)
#pragma unroll
                for (int j = 0; j < 4; j++) ffma2(acc[i][j], xa[i], wb[j]);
        }
        __syncthreads();
    }
#pragma unroll
    for (int i = 0; i < 4; i++)
#pragma unroll
        for (int j = 0; j < 4; j++) {
            int m = m0 + tm + 16 * i, n = n0 + tn + 16 * j;
            g_enc_proj[m * A + n] = unpack_sum(acc[i][j]);
        }
}

// ---------------- per-step: scores + seed out bias + zero gates ------------
// grid (B, 8 s-chunks); each warp does 2 s-rows.
__global__ void __launch_bounds__(256) k_score(const float* __restrict__ v_att,
                                               const float* __restrict__ bout,
                                               float* __restrict__ out, int step) {
    __shared__ float sh_dec[A];
    __shared__ float sh_v[A];
    int b = blockIdx.x, sc = blockIdx.y, tid = threadIdx.x;
    sh_dec[tid] = g_dec[b * A + tid];
    sh_v[tid]   = v_att[tid];
    // seed out[b, step, :] with bias (before out-GEMM atomics)
    {
        int n = sc * 1024 + tid * 4;
        *(float4*)&out[(b * T + step) * V + n] = *(const float4*)&bout[n];
    }
    // zero gates for split-K atomics (512 blocks x 256 = B*G4 exactly)
    g_gates[(b * 8 + sc) * 256 + tid] = 0.f;
    __syncthreads();

    int wid = tid >> 5, lane = tid & 31;
#pragma unroll
    for (int r = 0; r < 2; r++) {
        int s = sc * 16 + wid * 2 + r;
        const float* ep = &g_enc_proj[(b * S + s) * A];
        float p = 0.f;
#pragma unroll
        for (int q = 0; q < 8; q++) {
            int a = lane + 32 * q;
            p += fast_tanh(ep[a] + sh_dec[a]) * sh_v[a];
        }
#pragma unroll
        for (int off = 16; off; off >>= 1) p += __shfl_down_sync(0xffffffffu, p, off);
        if (lane == 0) g_scores[b * S + s] = p;
    }
}

// ---------------- per-step: softmax + context + assemble xcat --------------
// grid (B, 4 e-chunks); softmax recomputed per block (cheap); s split in halves.
__global__ void __launch_bounds__(256) k_softctx(const float* __restrict__ enc, int step) {
    __shared__ float sw[S];
    __shared__ float sacc[256];
    __shared__ float sred;
    int b = blockIdx.x, ec = blockIdx.y, tid = threadIdx.x;
    if (tid < S) sw[tid] = g_scores[b * S + tid];
    __syncthreads();
    if (tid < 32) {
        float m = fmaxf(fmaxf(sw[tid], sw[tid + 32]), fmaxf(sw[tid + 64], sw[tid + 96]));
#pragma unroll
        for (int off = 16; off; off >>= 1) m = fmaxf(m, __shfl_xor_sync(0xffffffffu, m, off));
        if (tid == 0) sred = m;
    }
    __syncthreads();
    float mx = sred;
    if (tid < S) sw[tid] = expf(sw[tid] - mx);
    __syncthreads();
    if (tid < 32) {
        float ssum = sw[tid] + sw[tid + 32] + sw[tid + 64] + sw[tid + 96];
#pragma unroll
        for (int off = 16; off; off >>= 1) ssum += __shfl_xor_sync(0xffffffffu, ssum, off);
        if (tid == 0) sred = 1.f / ssum;
    }
    __syncthreads();
    float rinv = sred;

    // ctx[e] for e-chunk; 2 threads per e over s-halves
    int e  = ec * 128 + (tid & 127);
    int sh = tid >> 7;                // 0/1
    float acc = 0.f;
    const float* eb = &enc[b * S * E + sh * 64 * E + e];
#pragma unroll 8
    for (int s = 0; s < 64; s++)
        acc += sw[sh * 64 + s] * eb[s * E];
    sacc[tid] = acc;
    __syncthreads();
    if (tid < 128) {
        float v = (sacc[tid] + sacc[tid + 128]) * rinv;
        g_xcat[b * HE + H + ec * 128 + tid] = v;
        g_hctx[b * HE + H + ec * 128 + tid] = v;
    }
    // x_emb -> xcat[:, :H] (blocks ec 0/1 cover 512)
    if (ec < 2)
        g_xcat[b * HE + ec * 256 + tid] = g_xemb[(step * B + b) * H + ec * 256 + tid];
}

// ---------------- warp-layout GEMM: C[64,N] += X1@W1^T (+X2@W2^T) ----------
// tile 64m x 128n; warp owns 8 m-rows (X via broadcast LDS); lane owns 4 n at
// stride 32 (pad-34 rows -> conflict-free). split-K via atomics (C pre-seeded).
__global__ void __launch_bounds__(256) k_wgemm(
    const float* __restrict__ X1, int ld1, int nc1,
    const float* __restrict__ W1, int lw1,
    const float* __restrict__ X2, int ld2, int nc2,
    const float* __restrict__ W2, int lw2,
    float* __restrict__ C, int ldc, int nsplit)
{
    __shared__ __align__(16) float Xs[64 * 34];
    __shared__ __align__(16) float Ws[128 * 34];
    int t = threadIdx.x, warp = t >> 5, lane = t & 31;
    int n0 = blockIdx.x * 128;
    ull acc[8][4];
#pragma unroll
    for (int i = 0; i < 8; i++)
#pragma unroll
        for (int j = 0; j < 4; j++) acc[i][j] = 0ull;

    int kk = t & 31, r = t >> 5;
    int total = nc1 + nc2;
    for (int cch = blockIdx.y; cch < total; cch += nsplit) {
        const float *X, *W; int ldx, ldw, k0;
        if (cch < nc1) { X = X1; W = W1; ldx = ld1; ldw = lw1; k0 = cch * 32; }
        else           { X = X2; W = W2; ldx = ld2; ldw = lw2; k0 = (cch - nc1) * 32; }
#pragma unroll
        for (int i = 0; i < 8; i++)
            Xs[(r + 8 * i) * 34 + kk] = X[(r + 8 * i) * ldx + k0 + kk];
#pragma unroll
        for (int i = 0; i < 16; i++)
            Ws[(r + 8 * i) * 34 + kk] = W[(n0 + r + 8 * i) * ldw + k0 + kk];
        __syncthreads();
#pragma unroll
        for (int kp = 0; kp < 16; kp++) {
            ull xa[8], wb[4];
#pragma unroll
            for (int i = 0; i < 8; i++)
                xa[i] = *(const ull*)&Xs[(warp * 8 + i) * 34 + 2 * kp];
#pragma unroll
            for (int j = 0; j < 4; j++)
                wb[j] = *(const ull*)&Ws[(lane + 32 * j) * 34 + 2 * kp];
#pragma unroll
            for (int i = 0; i < 8; i++)
#pragma unroll
                for (int j = 0; j < 4; j++) ffma2(acc[i][j], xa[i], wb[j]);
        }
        __syncthreads();
    }
#pragma unroll
    for (int i = 0; i < 8; i++)
#pragma unroll
        for (int j = 0; j < 4; j++)
            atomicAdd(&C[(warp * 8 + i) * ldc + n0 + 32 * j + lane],
                      unpack_sum(acc[i][j]));
}

// ---------------- per-step: LSTM cell update + seed next dec ---------------
__global__ void k_lstm(const float* __restrict__ b_att) {
    int idx = blockIdx.x * 256 + threadIdx.x;   // B*H = 32768
    int b = idx >> 9, j = idx & 511;
    const float* gr = &g_gates[b * G4];
    float gi = gr[j]         + g_bias[j];
    float gf = gr[j + 512]   + g_bias[j + 512];
    float gg = gr[j + 1024]  + g_bias[j + 1024];
    float go = gr[j + 1536]  + g_bias[j + 1536];
    float si = 1.f / (1.f + expf(-gi));
    float sf = 1.f / (1.f + expf(-gf));
    float so = 1.f / (1.f + expf(-go));
    float c  = sf * g_c[idx] + si * tanhf(gg);
    float hn = so * tanhf(c);
    g_c[idx] = c;
    g_h[idx] = hn;
    g_hctx[b * HE + j] = hn;
    if (idx < B * A) g_dec[idx] = b_att[idx & (A - 1)];   // seed next step's dec
}

// ---------------- launch ----------------------------------------------------
extern "C" void kernel_launch(void* const* d_in, const int* in_sizes, int n_in,
                              void* d_out, int out_size) {
    const float* enc  = (const float*)d_in[0];
    const int*   tgt  = (const int*)  d_in[1];
    const float* emb  = (const float*)d_in[2];
    const float* Wenc = (const float*)d_in[3];
    const float* Wdec = (const float*)d_in[4];
    const float* batt = (const float*)d_in[5];
    const float* vatt = (const float*)d_in[6];
    const float* Wih  = (const float*)d_in[7];
    const float* Whh  = (const float*)d_in[8];
    const float* bih  = (const float*)d_in[9];
    const float* bhh  = (const float*)d_in[10];
    const float* Wout = (const float*)d_in[11];
    const float* bout = (const float*)d_in[12];
    float* out = (float*)d_out;

    float *xcat, *hctx, *gates, *hbuf, *dec, *wdecT;
    cudaGetSymbolAddress((void**)&xcat,  g_xcat);
    cudaGetSymbolAddress((void**)&hctx,  g_hctx);
    cudaGetSymbolAddress((void**)&gates, g_gates);
    cudaGetSymbolAddress((void**)&hbuf,  g_h);
    cudaGetSymbolAddress((void**)&dec,   g_dec);
    cudaGetSymbolAddress((void**)&wdecT, g_WdecT);

    k_init<<<128, 256>>>(bih, bhh, batt);
    k_transpose<<<(A * H) / 256, 256>>>(Wdec);
    k_embed<<<(T * B * H) / 256, 256>>>(tgt, emb);
    k_encproj<<<dim3(A / 64, (B * S) / 64), 256>>>(enc, Wenc);

    for (int t = 0; t < T; t++) {
        // dec += h@WdecT^T (split-K=8; seeded with b_att in k_init/k_lstm)
        k_wgemm<<<dim3(A / 128, 8), 256>>>(hbuf, H, H / 32, wdecT, H,
                                           nullptr, 0, 0, nullptr, 0,
                                           dec, A, 8);
        k_score<<<dim3(B, 8), 256>>>(vatt, bout, out, t);
        k_softctx<<<dim3(B, 4), 256>>>(enc, t);
        // gates += xcat@W_ih^T + h@W_hh^T  (split-K=8; zeroed in k_score)
        k_wgemm<<<dim3(G4 / 128, 8), 256>>>(xcat, HE, HE / 32, Wih, HE,
                                            hbuf, H,  H / 32,  Whh, H,
                                            gates, G4, 8);
        k_lstm<<<(B * H) / 256, 256>>>(batt);
        // out[:, t, :] += hctx@W_out^T  (split-K=4; bias seeded in k_score)
        k_wgemm<<<dim3(V / 128, 4), 256>>>(hctx, HE, HE / 32, Wout, HE,
                                           nullptr, 0, 0, nullptr, 0,
                                           out + t * V, T * V, 4);
    }
}

// round 4
// speedup vs baseline: 2.3576x; 1.3434x over previous
#include <cuda_runtime.h>

#define B 64
#define S 128
#define E 512
#define H 512
#define A 256
#define V 8192
#define T 32
#define HE 1024   /* H + E */
#define G4 2048   /* 4*H   */

typedef unsigned long long ull;

// ---------------- persistent device scratch (no allocations allowed) -------
__device__ float g_enc_proj[B * S * A];   // 8 MB
__device__ float g_xemb[T * B * H];       // 4 MB
__device__ float g_hist[T * B * HE];      // 8 MB  [t*B+b][ h | ctx ]
__device__ float g_WdecT[A * H];
__device__ float g_WencT[A * E];
__device__ float g_dec[B * A];
__device__ float g_scores[B * S];
__device__ float g_h[B * H];
__device__ float g_c[B * H];
__device__ float g_xcat[B * HE];          // [x_emb | ctx]
__device__ float g_gates[B * G4];
__device__ float g_bias[G4];              // b_ih + b_hh

// ---------------- helpers --------------------------------------------------
__device__ __forceinline__ float fast_tanh(float x) {
    float r; asm("tanh.approx.f32 %0, %1;" : "=f"(r) : "f"(x)); return r;
}
__device__ __forceinline__ void ffma2(ull& d, ull a, ull b) {
    asm("fma.rn.f32x2 %0, %1, %2, %0;" : "+l"(d) : "l"(a), "l"(b));
}
__device__ __forceinline__ float unpack_sum(ull a) {
    float lo = __uint_as_float((unsigned)(a & 0xffffffffull));
    float hi = __uint_as_float((unsigned)(a >> 32));
    return lo + hi;
}

// ---------------- init: h=c=0, fused bias, seed dec with b_att -------------
__global__ void k_init(const float* __restrict__ b_ih, const float* __restrict__ b_hh,
                       const float* __restrict__ b_att) {
    int idx = blockIdx.x * 256 + threadIdx.x;   // 32768 threads
    if (idx < B * H) { g_h[idx] = 0.f; g_c[idx] = 0.f; }
    if (idx < G4) g_bias[idx] = b_ih[idx] + b_hh[idx];
    if (idx < B * A) g_dec[idx] = b_att[idx & (A - 1)];
}

// ---------------- one-time transposes (k-major weights) --------------------
__global__ void k_transpose(const float* __restrict__ Win, float* __restrict__ Wt,
                            int rows, int cols) {           // Win[rows,cols] -> Wt[cols,rows]
    int idx = blockIdx.x * 256 + threadIdx.x;
    int c = idx / rows, r = idx % rows;
    Wt[c * rows + r] = Win[r * cols + c];
}

// ---------------- gather teacher-forced embeddings for ALL steps -----------
__global__ void k_embed(const int* __restrict__ tgt, const float* __restrict__ emb) {
    int idx = blockIdx.x * 256 + threadIdx.x;   // T*B*H = 1M
    int hh = idx & (H - 1);
    int rb = idx >> 9;          // t*B + b
    int b  = rb & (B - 1);
    int t  = rb >> 6;
    int tok = (t == 0) ? 0 : tgt[b * T + (t - 1)];
    g_xemb[idx] = emb[tok * H + hh];
}

// ---------------- big GEMM: C = X[M,K] @ W[N,K]^T (+bias), warp layout -----
// tile 64m x 128n x 32k; warp owns 8 m-rows (broadcast LDS), lane owns 4 n at
// stride 32. Full-K loop (no split, no atomics). Optional row permute:
// global row m -> out row (m&63)*T + (m>>6)   (maps t*B+b -> b*T+t).
__global__ void __launch_bounds__(256, 2) k_bgemm(
    const float* __restrict__ X, int ldx,
    const float* __restrict__ W, int ldw, int kchunks,
    float* __restrict__ C, int ldc,
    const float* __restrict__ bias, int permute)
{
    __shared__ __align__(16) float Xs[64 * 34];
    __shared__ __align__(16) float Ws[128 * 34];
    int t = threadIdx.x, warp = t >> 5, lane = t & 31;
    int n0 = blockIdx.x * 128, m0 = blockIdx.y * 64;
    ull acc[8][4];
#pragma unroll
    for (int i = 0; i < 8; i++)
#pragma unroll
        for (int j = 0; j < 4; j++) acc[i][j] = 0ull;

    int kk = t & 31, r = t >> 5;
    for (int cch = 0; cch < kchunks; cch++) {
        int k0 = cch * 32;
#pragma unroll
        for (int i = 0; i < 8; i++)
            Xs[(r + 8 * i) * 34 + kk] = X[(m0 + r + 8 * i) * ldx + k0 + kk];
#pragma unroll
        for (int i = 0; i < 16; i++)
            Ws[(r + 8 * i) * 34 + kk] = W[(n0 + r + 8 * i) * ldw + k0 + kk];
        __syncthreads();
#pragma unroll
        for (int kp = 0; kp < 16; kp++) {
            ull xa[8], wb[4];
#pragma unroll
            for (int i = 0; i < 8; i++)
                xa[i] = *(const ull*)&Xs[(warp * 8 + i) * 34 + 2 * kp];
#pragma unroll
            for (int j = 0; j < 4; j++)
                wb[j] = *(const ull*)&Ws[(lane + 32 * j) * 34 + 2 * kp];
#pragma unroll
            for (int i = 0; i < 8; i++)
#pragma unroll
                for (int j = 0; j < 4; j++) ffma2(acc[i][j], xa[i], wb[j]);
        }
        __syncthreads();
    }
#pragma unroll
    for (int i = 0; i < 8; i++) {
        int m = m0 + warp * 8 + i;
        int row = permute ? ((m & 63) * T + (m >> 6)) : m;
#pragma unroll
        for (int j = 0; j < 4; j++) {
            int n = n0 + 32 * j + lane;
            C[row * ldc + n] = unpack_sum(acc[i][j]) + (bias ? bias[n] : 0.f);
        }
    }
}

// ---------------- per-step: scores + zero gates ----------------------------
// grid (B, 8 s-chunks); each warp does 2 s-rows.
__global__ void __launch_bounds__(256) k_score(const float* __restrict__ v_att) {
    __shared__ float sh_dec[A];
    __shared__ float sh_v[A];
    int b = blockIdx.x, sc = blockIdx.y, tid = threadIdx.x;
    sh_dec[tid] = g_dec[b * A + tid];
    sh_v[tid]   = v_att[tid];
    // zero gates for split-K atomics (512 blocks x 256 = B*G4 exactly)
    g_gates[(b * 8 + sc) * 256 + tid] = 0.f;
    __syncthreads();

    int wid = tid >> 5, lane = tid & 31;
#pragma unroll
    for (int r = 0; r < 2; r++) {
        int s = sc * 16 + wid * 2 + r;
        const float* ep = &g_enc_proj[(b * S + s) * A];
        float p = 0.f;
#pragma unroll
        for (int q = 0; q < 8; q++) {
            int a = lane + 32 * q;
            p += fast_tanh(ep[a] + sh_dec[a]) * sh_v[a];
        }
#pragma unroll
        for (int off = 16; off; off >>= 1) p += __shfl_down_sync(0xffffffffu, p, off);
        if (lane == 0) g_scores[b * S + s] = p;
    }
}

// ---------------- per-step: softmax + context + assemble xcat/hist ---------
__global__ void __launch_bounds__(256) k_softctx(const float* __restrict__ enc, int step) {
    __shared__ float sw[S];
    __shared__ float sacc[256];
    __shared__ float sred;
    int b = blockIdx.x, ec = blockIdx.y, tid = threadIdx.x;
    if (tid < S) sw[tid] = g_scores[b * S + tid];
    __syncthreads();
    if (tid < 32) {
        float m = fmaxf(fmaxf(sw[tid], sw[tid + 32]), fmaxf(sw[tid + 64], sw[tid + 96]));
#pragma unroll
        for (int off = 16; off; off >>= 1) m = fmaxf(m, __shfl_xor_sync(0xffffffffu, m, off));
        if (tid == 0) sred = m;
    }
    __syncthreads();
    float mx = sred;
    if (tid < S) sw[tid] = expf(sw[tid] - mx);
    __syncthreads();
    if (tid < 32) {
        float ssum = sw[tid] + sw[tid + 32] + sw[tid + 64] + sw[tid + 96];
#pragma unroll
        for (int off = 16; off; off >>= 1) ssum += __shfl_xor_sync(0xffffffffu, ssum, off);
        if (tid == 0) sred = 1.f / ssum;
    }
    __syncthreads();
    float rinv = sred;

    // ctx[e] for e-chunk; 2 threads per e over s-halves
    int e  = ec * 128 + (tid & 127);
    int sh = tid >> 7;                // 0/1
    float acc = 0.f;
    const float* eb = &enc[b * S * E + sh * 64 * E + e];
#pragma unroll 8
    for (int s = 0; s < 64; s++)
        acc += sw[sh * 64 + s] * eb[s * E];
    sacc[tid] = acc;
    __syncthreads();
    if (tid < 128) {
        float v = (sacc[tid] + sacc[tid + 128]) * rinv;
        g_xcat[b * HE + H + ec * 128 + tid] = v;
        g_hist[(step * B + b) * HE + H + ec * 128 + tid] = v;
    }
    // x_emb -> xcat[:, :H] (blocks ec 0/1 cover 512)
    if (ec < 2)
        g_xcat[b * HE + ec * 256 + tid] = g_xemb[(step * B + b) * H + ec * 256 + tid];
}

// ---------------- warp-layout split-K GEMM (in-loop, M=64) -----------------
__global__ void __launch_bounds__(256) k_wgemm(
    const float* __restrict__ X1, int ld1, int nc1,
    const float* __restrict__ W1, int lw1,
    const float* __restrict__ X2, int ld2, int nc2,
    const float* __restrict__ W2, int lw2,
    float* __restrict__ C, int ldc, int nsplit)
{
    __shared__ __align__(16) float Xs[64 * 34];
    __shared__ __align__(16) float Ws[128 * 34];
    int t = threadIdx.x, warp = t >> 5, lane = t & 31;
    int n0 = blockIdx.x * 128;
    ull acc[8][4];
#pragma unroll
    for (int i = 0; i < 8; i++)
#pragma unroll
        for (int j = 0; j < 4; j++) acc[i][j] = 0ull;

    int kk = t & 31, r = t >> 5;
    int total = nc1 + nc2;
    for (int cch = blockIdx.y; cch < total; cch += nsplit) {
        const float *X, *W; int ldx, ldw, k0;
        if (cch < nc1) { X = X1; W = W1; ldx = ld1; ldw = lw1; k0 = cch * 32; }
        else           { X = X2; W = W2; ldx = ld2; ldw = lw2; k0 = (cch - nc1) * 32; }
#pragma unroll
        for (int i = 0; i < 8; i++)
            Xs[(r + 8 * i) * 34 + kk] = X[(r + 8 * i) * ldx + k0 + kk];
#pragma unroll
        for (int i = 0; i < 16; i++)
            Ws[(r + 8 * i) * 34 + kk] = W[(n0 + r + 8 * i) * ldw + k0 + kk];
        __syncthreads();
#pragma unroll
        for (int kp = 0; kp < 16; kp++) {
            ull xa[8], wb[4];
#pragma unroll
            for (int i = 0; i < 8; i++)
                xa[i] = *(const ull*)&Xs[(warp * 8 + i) * 34 + 2 * kp];
#pragma unroll
            for (int j = 0; j < 4; j++)
                wb[j] = *(const ull*)&Ws[(lane + 32 * j) * 34 + 2 * kp];
#pragma unroll
            for (int i = 0; i < 8; i++)
#pragma unroll
                for (int j = 0; j < 4; j++) ffma2(acc[i][j], xa[i], wb[j]);
        }
        __syncthreads();
    }
#pragma unroll
    for (int i = 0; i < 8; i++)
#pragma unroll
        for (int j = 0; j < 4; j++)
            atomicAdd(&C[(warp * 8 + i) * ldc + n0 + 32 * j + lane],
                      unpack_sum(acc[i][j]));
}

// ---------------- per-step: LSTM cell update + hist + seed next dec --------
__global__ void k_lstm(const float* __restrict__ b_att, int step) {
    int idx = blockIdx.x * 256 + threadIdx.x;   // B*H = 32768
    int b = idx >> 9, j = idx & 511;
    const float* gr = &g_gates[b * G4];
    float gi = gr[j]         + g_bias[j];
    float gf = gr[j + 512]   + g_bias[j + 512];
    float gg = gr[j + 1024]  + g_bias[j + 1024];
    float go = gr[j + 1536]  + g_bias[j + 1536];
    float si = 1.f / (1.f + expf(-gi));
    float sf = 1.f / (1.f + expf(-gf));
    float so = 1.f / (1.f + expf(-go));
    float c  = sf * g_c[idx] + si * tanhf(gg);
    float hn = so * tanhf(c);
    g_c[idx] = c;
    g_h[idx] = hn;
    g_hist[(step * B + b) * HE + j] = hn;
    if (idx < B * A) g_dec[idx] = b_att[idx & (A - 1)];   // seed next step's dec
}

// ---------------- launch ----------------------------------------------------
extern "C" void kernel_launch(void* const* d_in, const int* in_sizes, int n_in,
                              void* d_out, int out_size) {
    const float* enc  = (const float*)d_in[0];
    const int*   tgt  = (const int*)  d_in[1];
    const float* emb  = (const float*)d_in[2];
    const float* Wenc = (const float*)d_in[3];
    const float* Wdec = (const float*)d_in[4];
    const float* batt = (const float*)d_in[5];
    const float* vatt = (const float*)d_in[6];
    const float* Wih  = (const float*)d_in[7];
    const float* Whh  = (const float*)d_in[8];
    const float* bih  = (const float*)d_in[9];
    const float* bhh  = (const float*)d_in[10];
    const float* Wout = (const float*)d_in[11];
    const float* bout = (const float*)d_in[12];
    float* out = (float*)d_out;

    float *xcat, *gates, *hbuf, *dec, *wdecT, *wencT, *encp, *hist;
    cudaGetSymbolAddress((void**)&xcat,  g_xcat);
    cudaGetSymbolAddress((void**)&gates, g_gates);
    cudaGetSymbolAddress((void**)&hbuf,  g_h);
    cudaGetSymbolAddress((void**)&dec,   g_dec);
    cudaGetSymbolAddress((void**)&wdecT, g_WdecT);
    cudaGetSymbolAddress((void**)&wencT, g_WencT);
    cudaGetSymbolAddress((void**)&encp,  g_enc_proj);
    cudaGetSymbolAddress((void**)&hist,  g_hist);

    k_init<<<128, 256>>>(bih, bhh, batt);
    k_transpose<<<(A * H) / 256, 256>>>(Wdec, wdecT, H, A);
    k_transpose<<<(A * E) / 256, 256>>>(Wenc, wencT, E, A);
    k_embed<<<(T * B * H) / 256, 256>>>(tgt, emb);
    // enc_proj[8192, 256] = enc[8192,512] @ WencT[256,512]^T
    k_bgemm<<<dim3(A / 128, (B * S) / 64), 256>>>(enc, E, wencT, E, E / 32,
                                                  encp, A, nullptr, 0);

    for (int t = 0; t < T; t++) {
        // dec += h@WdecT^T (split-K=16; seeded with b_att in k_init/k_lstm)
        k_wgemm<<<dim3(A / 128, 16), 256>>>(hbuf, H, H / 32, wdecT, H,
                                            nullptr, 0, 0, nullptr, 0,
                                            dec, A, 16);
        k_score<<<dim3(B, 8), 256>>>(vatt);
        k_softctx<<<dim3(B, 4), 256>>>(enc, t);
        // gates += xcat@W_ih^T + h@W_hh^T  (split-K=8; zeroed in k_score)
        k_wgemm<<<dim3(G4 / 128, 8), 256>>>(xcat, HE, HE / 32, Wih, HE,
                                            hbuf, H,  H / 32,  Whh, H,
                                            gates, G4, 8);
        k_lstm<<<(B * H) / 256, 256>>>(batt, t);
    }
    // out[b, t, :] = hist[t*B+b] @ W_out^T + b_out  (one batched GEMM)
    k_bgemm<<<dim3(V / 128, (T * B) / 64), 256>>>(hist, HE, Wout, HE, HE / 32,
                                                  out, V, bout, 1);
}

// round 8
// speedup vs baseline: 2.8678x; 1.2164x over previous
#include <cuda_runtime.h>
#include <cstdint>

#define B 64
#define S 128
#define E 512
#define H 512
#define A 256
#define V 8192
#define T 32
#define HE 1024   /* H + E */
#define G4 2048   /* 4*H   */

typedef unsigned long long ull;

// ---------------- persistent device scratch (no allocations allowed) -------
__device__ float g_enc_proj[B * S * A];   // 8 MB
__device__ float g_xemb[T * B * H];       // 4 MB
__device__ float g_hist[T * B * HE];      // 8 MB  [t*B+b][ h | ctx ]
__device__ unsigned short g_histH[T * B * HE];  // 4 MB bf16 hi
__device__ unsigned short g_histL[T * B * HE];  // 4 MB bf16 lo
__device__ unsigned short g_WoutH[V * HE];      // 16 MB
__device__ unsigned short g_WoutL[V * HE];      // 16 MB
__device__ float g_WdecT[A * H];
__device__ float g_WencT[A * E];
__device__ float g_dec[B * A];
__device__ float g_h[B * H];
__device__ float g_c[B * H];
__device__ float g_xcat[B * HE];          // [x_emb | ctx]
__device__ float g_gates[B * G4];
__device__ float g_bias[G4];              // b_ih + b_hh

// ---------------- helpers --------------------------------------------------
__device__ __forceinline__ float fast_tanh(float x) {
    float r; asm("tanh.approx.f32 %0, %1;" : "=f"(r) : "f"(x)); return r;
}
__device__ __forceinline__ void ffma2(ull& d, ull a, ull b) {
    asm("fma.rn.f32x2 %0, %1, %2, %0;" : "+l"(d) : "l"(a), "l"(b));
}
__device__ __forceinline__ float unpack_sum(ull a) {
    float lo = __uint_as_float((unsigned)(a & 0xffffffffull));
    float hi = __uint_as_float((unsigned)(a >> 32));
    return lo + hi;
}
// pack (x0,x1) -> bf16x2 hi, residuals -> bf16x2 lo
__device__ __forceinline__ unsigned packhl(float x0, float x1, unsigned& lo_out) {
    unsigned hi;
    asm("cvt.rn.bf16x2.f32 %0, %1, %2;" : "=r"(hi) : "f"(x1), "f"(x0));
    float h0 = __uint_as_float(hi << 16);
    float h1 = __uint_as_float(hi & 0xffff0000u);
    float l0 = x0 - h0, l1 = x1 - h1;
    asm("cvt.rn.bf16x2.f32 %0, %1, %2;" : "=r"(lo_out) : "f"(l1), "f"(l0));
    return hi;
}
__device__ __forceinline__ void mma16816(float* c, uint32_t a0, uint32_t a1,
                                         uint32_t a2, uint32_t a3,
                                         uint32_t b0, uint32_t b1) {
    asm volatile(
        "mma.sync.aligned.m16n8k16.row.col.f32.bf16.bf16.f32 "
        "{%0,%1,%2,%3}, {%4,%5,%6,%7}, {%8,%9}, {%0,%1,%2,%3};"
        : "+f"(c[0]), "+f"(c[1]), "+f"(c[2]), "+f"(c[3])
        : "r"(a0), "r"(a1), "r"(a2), "r"(a3), "r"(b0), "r"(b1));
}

// ---------------- init: h=c=0, fused bias, seed dec with b_att -------------
__global__ void k_init(const float* __restrict__ b_ih, const float* __restrict__ b_hh,
                       const float* __restrict__ b_att) {
    int idx = blockIdx.x * 256 + threadIdx.x;
    if (idx < B * H) { g_h[idx] = 0.f; g_c[idx] = 0.f; }
    if (idx < G4) g_bias[idx] = b_ih[idx] + b_hh[idx];
    if (idx < B * A) g_dec[idx] = b_att[idx & (A - 1)];
}

// ---------------- one-time transposes (k-major weights) --------------------
__global__ void k_transpose(const float* __restrict__ Win, float* __restrict__ Wt,
                            int rows, int cols) {
    int idx = blockIdx.x * 256 + threadIdx.x;
    int c = idx / rows, r = idx % rows;
    Wt[c * rows + r] = Win[r * cols + c];
}

// ---------------- fp32 -> (hi, lo) bf16 split, 2 elems/thread --------------
__global__ void k_cvt(const float* __restrict__ src,
                      unsigned short* __restrict__ dh,
                      unsigned short* __restrict__ dl) {
    int i = (blockIdx.x * 256 + threadIdx.x) * 2;
    float2 f = *(const float2*)&src[i];
    unsigned lo, hi = packhl(f.x, f.y, lo);
    *(unsigned*)&dh[i] = hi;
    *(unsigned*)&dl[i] = lo;
}

// ---------------- gather teacher-forced embeddings for ALL steps -----------
__global__ void k_embed(const int* __restrict__ tgt, const float* __restrict__ emb) {
    int idx = blockIdx.x * 256 + threadIdx.x;   // T*B*H = 1M
    int hh = idx & (H - 1);
    int rb = idx >> 9;
    int b  = rb & (B - 1);
    int t  = rb >> 6;
    int tok = (t == 0) ? 0 : tgt[b * T + (t - 1)];
    g_xemb[idx] = emb[tok * H + hh];
}

// ---------------- fp32 GEMM (warp layout) for enc_proj ---------------------
__global__ void __launch_bounds__(256, 2) k_bgemm(
    const float* __restrict__ X, int ldx,
    const float* __restrict__ W, int ldw, int kchunks,
    float* __restrict__ C, int ldc)
{
    __shared__ __align__(16) float Xs[64 * 34];
    __shared__ __align__(16) float Ws[128 * 34];
    int t = threadIdx.x, warp = t >> 5, lane = t & 31;
    int n0 = blockIdx.x * 128, m0 = blockIdx.y * 64;
    ull acc[8][4];
#pragma unroll
    for (int i = 0; i < 8; i++)
#pragma unroll
        for (int j = 0; j < 4; j++) acc[i][j] = 0ull;

    int kk = t & 31, r = t >> 5;
    for (int cch = 0; cch < kchunks; cch++) {
        int k0 = cch * 32;
#pragma unroll
        for (int i = 0; i < 8; i++)
            Xs[(r + 8 * i) * 34 + kk] = X[(m0 + r + 8 * i) * ldx + k0 + kk];
#pragma unroll
        for (int i = 0; i < 16; i++)
            Ws[(r + 8 * i) * 34 + kk] = W[(n0 + r + 8 * i) * ldw + k0 + kk];
        __syncthreads();
#pragma unroll
        for (int kp = 0; kp < 16; kp++) {
            ull xa[8], wb[4];
#pragma unroll
            for (int i = 0; i < 8; i++)
                xa[i] = *(const ull*)&Xs[(warp * 8 + i) * 34 + 2 * kp];
#pragma unroll
            for (int j = 0; j < 4; j++)
                wb[j] = *(const ull*)&Ws[(lane + 32 * j) * 34 + 2 * kp];
#pragma unroll
            for (int i = 0; i < 8; i++)
#pragma unroll
                for (int j = 0; j < 4; j++) ffma2(acc[i][j], xa[i], wb[j]);
        }
        __syncthreads();
    }
#pragma unroll
    for (int i = 0; i < 8; i++)
#pragma unroll
        for (int j = 0; j < 4; j++)
            C[(m0 + warp * 8 + i) * ldc + n0 + 32 * j + lane] = unpack_sum(acc[i][j]);
}

// ---------------- per-step FUSED: scores + softmax + ctx + xcat ------------
// grid B, 512 threads.
__global__ void __launch_bounds__(512) k_attn(const float* __restrict__ v_att,
                                              const float* __restrict__ enc, int step) {
    __shared__ float sh_dec[A];
    __shared__ float sh_v[A];
    __shared__ float sw[S];
    __shared__ float sred;
    int b = blockIdx.x, tid = threadIdx.x;
    if (tid < A) { sh_dec[tid] = g_dec[b * A + tid]; sh_v[tid] = v_att[tid]; }
    // zero gates for split-K atomics (512 thr x 4 = G4 exactly)
    *(float4*)&g_gates[b * G4 + tid * 4] = make_float4(0.f, 0.f, 0.f, 0.f);
    __syncthreads();

    int wid = tid >> 5, lane = tid & 31;
#pragma unroll
    for (int r = 0; r < 8; r++) {             // 16 warps x 8 = 128 s-rows
        int s = wid * 8 + r;
        const float* ep = &g_enc_proj[(b * S + s) * A];
        float p = 0.f;
#pragma unroll
        for (int q = 0; q < 8; q++) {
            int a = lane + 32 * q;
            p += fast_tanh(ep[a] + sh_dec[a]) * sh_v[a];
        }
#pragma unroll
        for (int off = 16; off; off >>= 1) p += __shfl_down_sync(0xffffffffu, p, off);
        if (lane == 0) sw[s] = p;
    }
    __syncthreads();
    if (tid < 32) {
        float m = fmaxf(fmaxf(sw[tid], sw[tid + 32]), fmaxf(sw[tid + 64], sw[tid + 96]));
#pragma unroll
        for (int off = 16; off; off >>= 1) m = fmaxf(m, __shfl_xor_sync(0xffffffffu, m, off));
        if (tid == 0) sred = m;
    }
    __syncthreads();
    float mx = sred;
    if (tid < S) sw[tid] = expf(sw[tid] - mx);
    __syncthreads();
    if (tid < 32) {
        float ssum = sw[tid] + sw[tid + 32] + sw[tid + 64] + sw[tid + 96];
#pragma unroll
        for (int off = 16; off; off >>= 1) ssum += __shfl_xor_sync(0xffffffffu, ssum, off);
        if (tid == 0) sred = 1.f / ssum;
    }
    __syncthreads();
    float rinv = sred;

    // ctx[e]: one e per thread (512), coalesced over s
    float acc = 0.f;
    const float* eb = &enc[b * S * E + tid];
#pragma unroll 8
    for (int s = 0; s < S; s++)
        acc += sw[s] * eb[s * E];
    float v = acc * rinv;
    g_xcat[b * HE + H + tid] = v;
    g_hist[(step * B + b) * HE + H + tid] = v;
    // x_emb -> xcat[:, :H]
    g_xcat[b * HE + tid] = g_xemb[(step * B + b) * H + tid];
}

// ---------------- warp-layout split-K GEMM (in-loop, M=64) -----------------
__global__ void __launch_bounds__(256) k_wgemm(
    const float* __restrict__ X1, int ld1, int nc1,
    const float* __restrict__ W1, int lw1,
    const float* __restrict__ X2, int ld2, int nc2,
    const float* __restrict__ W2, int lw2,
    float* __restrict__ C, int ldc, int nsplit)
{
    __shared__ __align__(16) float Xs[64 * 34];
    __shared__ __align__(16) float Ws[128 * 34];
    int t = threadIdx.x, warp = t >> 5, lane = t & 31;
    int n0 = blockIdx.x * 128;
    ull acc[8][4];
#pragma unroll
    for (int i = 0; i < 8; i++)
#pragma unroll
        for (int j = 0; j < 4; j++) acc[i][j] = 0ull;

    int kk = t & 31, r = t >> 5;
    int total = nc1 + nc2;
    for (int cch = blockIdx.y; cch < total; cch += nsplit) {
        const float *X, *W; int ldx, ldw, k0;
        if (cch < nc1) { X = X1; W = W1; ldx = ld1; ldw = lw1; k0 = cch * 32; }
        else           { X = X2; W = W2; ldx = ld2; ldw = lw2; k0 = (cch - nc1) * 32; }
#pragma unroll
        for (int i = 0; i < 8; i++)
            Xs[(r + 8 * i) * 34 + kk] = X[(r + 8 * i) * ldx + k0 + kk];
#pragma unroll
        for (int i = 0; i < 16; i++)
            Ws[(r + 8 * i) * 34 + kk] = W[(n0 + r + 8 * i) * ldw + k0 + kk];
        __syncthreads();
#pragma unroll
        for (int kp = 0; kp < 16; kp++) {
            ull xa[8], wb[4];
#pragma unroll
            for (int i = 0; i < 8; i++)
                xa[i] = *(const ull*)&Xs[(warp * 8 + i) * 34 + 2 * kp];
#pragma unroll
            for (int j = 0; j < 4; j++)
                wb[j] = *(const ull*)&Ws[(lane + 32 * j) * 34 + 2 * kp];
#pragma unroll
            for (int i = 0; i < 8; i++)
#pragma unroll
                for (int j = 0; j < 4; j++) ffma2(acc[i][j], xa[i], wb[j]);
        }
        __syncthreads();
    }
#pragma unroll
    for (int i = 0; i < 8; i++)
#pragma unroll
        for (int j = 0; j < 4; j++)
            atomicAdd(&C[(warp * 8 + i) * ldc + n0 + 32 * j + lane],
                      unpack_sum(acc[i][j]));
}

// ---------------- per-step: LSTM cell update + hist + seed next dec --------
__global__ void k_lstm(const float* __restrict__ b_att, int step) {
    int idx = blockIdx.x * 256 + threadIdx.x;
    int b = idx >> 9, j = idx & 511;
    const float* gr = &g_gates[b * G4];
    float gi = gr[j]         + g_bias[j];
    float gf = gr[j + 512]   + g_bias[j + 512];
    float gg = gr[j + 1024]  + g_bias[j + 1024];
    float go = gr[j + 1536]  + g_bias[j + 1536];
    float si = 1.f / (1.f + expf(-gi));
    float sf = 1.f / (1.f + expf(-gf));
    float so = 1.f / (1.f + expf(-go));
    float c  = sf * g_c[idx] + si * tanhf(gg);
    float hn = so * tanhf(c);
    g_c[idx] = c;
    g_h[idx] = hn;
    g_hist[(step * B + b) * HE + j] = hn;
    if (idx < B * A) g_dec[idx] = b_att[idx & (A - 1)];
}

// ---------------- mma.sync bf16 3-term final GEMM --------------------------
// out[(m&63)*T + (m>>6)][n] = sum_k hist[m][k]*Wout[n][k] + bout[n]
// CTA tile 128m x 128n, 8 warps (2x4), warp tile 64x32, k-chunks of 32.
#define PADK 40   /* halves per smem row: 32 + 8 pad -> 80B stride, conflict-free */
__global__ void __launch_bounds__(256) k_mout(
    const unsigned short* __restrict__ Ahg, const unsigned short* __restrict__ Alg,
    const unsigned short* __restrict__ Bhg, const unsigned short* __restrict__ Blg,
    const float* __restrict__ bias, float* __restrict__ out)
{
    __shared__ __align__(16) unsigned short sAh[128 * PADK], sAl[128 * PADK];
    __shared__ __align__(16) unsigned short sBh[128 * PADK], sBl[128 * PADK];
    int tid = threadIdx.x, warp = tid >> 5, lane = tid & 31;
    int N0 = blockIdx.x * 128, M0 = blockIdx.y * 128;
    int wr = warp >> 2, wc = warp & 3;          // warp m-base wr*64, n-base wc*32
    float acc[4][4][4];
#pragma unroll
    for (int i = 0; i < 4; i++)
#pragma unroll
        for (int j = 0; j < 4; j++)
#pragma unroll
            for (int q = 0; q < 4; q++) acc[i][j][q] = 0.f;

    int cr = tid >> 1, ch = (tid & 1) * 16;     // copy: row, k-half (16 halves = 2x uint4)
    for (int kc = 0; kc < HE / 32; kc++) {
        int k0 = kc * 32;
        {
            const uint4* pa = (const uint4*)&Ahg[(size_t)(M0 + cr) * HE + k0 + ch];
            const uint4* pl = (const uint4*)&Alg[(size_t)(M0 + cr) * HE + k0 + ch];
            const uint4* pb = (const uint4*)&Bhg[(size_t)(N0 + cr) * HE + k0 + ch];
            const uint4* pbl= (const uint4*)&Blg[(size_t)(N0 + cr) * HE + k0 + ch];
            uint4* da = (uint4*)&sAh[cr * PADK + ch];
            uint4* dl = (uint4*)&sAl[cr * PADK + ch];
            uint4* db = (uint4*)&sBh[cr * PADK + ch];
            uint4* dbl= (uint4*)&sBl[cr * PADK + ch];
            da[0] = pa[0]; da[1] = pa[1];
            dl[0] = pl[0]; dl[1] = pl[1];
            db[0] = pb[0]; db[1] = pb[1];
            dbl[0]= pbl[0]; dbl[1]= pbl[1];
        }
        __syncthreads();
#pragma unroll
        for (int kq = 0; kq < 2; kq++) {
            int kb = kq * 16 + (lane & 3) * 2;
            uint32_t ah[4][4], al[4][4], bh[4][2], bl[4][2];
            int ar = wr * 64 + (lane >> 2);
#pragma unroll
            for (int mf = 0; mf < 4; mf++) {
                int r = ar + mf * 16;
                ah[mf][0] = *(const uint32_t*)&sAh[r * PADK + kb];
                ah[mf][1] = *(const uint32_t*)&sAh[(r + 8) * PADK + kb];
                ah[mf][2] = *(const uint32_t*)&sAh[r * PADK + kb + 8];
                ah[mf][3] = *(const uint32_t*)&sAh[(r + 8) * PADK + kb + 8];
                al[mf][0] = *(const uint32_t*)&sAl[r * PADK + kb];
                al[mf][1] = *(const uint32_t*)&sAl[(r + 8) * PADK + kb];
                al[mf][2] = *(const uint32_t*)&sAl[r * PADK + kb + 8];
                al[mf][3] = *(const uint32_t*)&sAl[(r + 8) * PADK + kb + 8];
            }
            int br = wc * 32 + (lane >> 2);
#pragma unroll
            for (int nf = 0; nf < 4; nf++) {
                int r = br + nf * 8;
                bh[nf][0] = *(const uint32_t*)&sBh[r * PADK + kb];
                bh[nf][1] = *(const uint32_t*)&sBh[r * PADK + kb + 8];
                bl[nf][0] = *(const uint32_t*)&sBl[r * PADK + kb];
                bl[nf][1] = *(const uint32_t*)&sBl[r * PADK + kb + 8];
            }
#pragma unroll
            for (int mf = 0; mf < 4; mf++)
#pragma unroll
                for (int nf = 0; nf < 4; nf++) {
                    mma16816(acc[mf][nf], ah[mf][0], ah[mf][1], ah[mf][2], ah[mf][3],
                             bh[nf][0], bh[nf][1]);
                    mma16816(acc[mf][nf], al[mf][0], al[mf][1], al[mf][2], al[mf][3],
                             bh[nf][0], bh[nf][1]);
                    mma16816(acc[mf][nf], ah[mf][0], ah[mf][1], ah[mf][2], ah[mf][3],
                             bl[nf][0], bl[nf][1]);
                }
        }
        __syncthreads();
    }
    // epilogue: direct permuted store + bias
#pragma unroll
    for (int mf = 0; mf < 4; mf++) {
        int m0g = M0 + wr * 64 + mf * 16 + (lane >> 2);
#pragma unroll
        for (int nf = 0; nf < 4; nf++) {
            int n = N0 + wc * 32 + nf * 8 + (lane & 3) * 2;
            float2 bia = *(const float2*)&bias[n];
            int r0 = (m0g & 63) * T + (m0g >> 6);
            int m1 = m0g + 8;
            int r1 = (m1 & 63) * T + (m1 >> 6);
            float2 v0 = make_float2(acc[mf][nf][0] + bia.x, acc[mf][nf][1] + bia.y);
            float2 v1 = make_float2(acc[mf][nf][2] + bia.x, acc[mf][nf][3] + bia.y);
            *(float2*)&out[(size_t)r0 * V + n] = v0;
            *(float2*)&out[(size_t)r1 * V + n] = v1;
        }
    }
}

// ---------------- launch ----------------------------------------------------
extern "C" void kernel_launch(void* const* d_in, const int* in_sizes, int n_in,
                              void* d_out, int out_size) {
    const float* enc  = (const float*)d_in[0];
    const int*   tgt  = (const int*)  d_in[1];
    const float* emb  = (const float*)d_in[2];
    const float* Wenc = (const float*)d_in[3];
    const float* Wdec = (const float*)d_in[4];
    const float* batt = (const float*)d_in[5];
    const float* vatt = (const float*)d_in[6];
    const float* Wih  = (const float*)d_in[7];
    const float* Whh  = (const float*)d_in[8];
    const float* bih  = (const float*)d_in[9];
    const float* bhh  = (const float*)d_in[10];
    const float* Wout = (const float*)d_in[11];
    const float* bout = (const float*)d_in[12];
    float* out = (float*)d_out;

    float *xcat, *gates, *hbuf, *dec, *wdecT, *wencT, *encp, *hist;
    unsigned short *hH, *hL, *wH, *wL;
    cudaGetSymbolAddress((void**)&xcat,  g_xcat);
    cudaGetSymbolAddress((void**)&gates, g_gates);
    cudaGetSymbolAddress((void**)&hbuf,  g_h);
    cudaGetSymbolAddress((void**)&dec,   g_dec);
    cudaGetSymbolAddress((void**)&wdecT, g_WdecT);
    cudaGetSymbolAddress((void**)&wencT, g_WencT);
    cudaGetSymbolAddress((void**)&encp,  g_enc_proj);
    cudaGetSymbolAddress((void**)&hist,  g_hist);
    cudaGetSymbolAddress((void**)&hH, g_histH);
    cudaGetSymbolAddress((void**)&hL, g_histL);
    cudaGetSymbolAddress((void**)&wH, g_WoutH);
    cudaGetSymbolAddress((void**)&wL, g_WoutL);

    k_init<<<128, 256>>>(bih, bhh, batt);
    k_transpose<<<(A * H) / 256, 256>>>(Wdec, wdecT, H, A);
    k_transpose<<<(A * E) / 256, 256>>>(Wenc, wencT, E, A);
    k_embed<<<(T * B * H) / 256, 256>>>(tgt, emb);
    k_cvt<<<(V * HE) / 512, 256>>>(Wout, wH, wL);
    // enc_proj[8192, 256] = enc[8192,512] @ WencT[256,512]^T
    k_bgemm<<<dim3(A / 128, (B * S) / 64), 256>>>(enc, E, wencT, E, E / 32, encp, A);

    for (int t = 0; t < T; t++) {
        // dec += h@WdecT^T (split-K=16; seeded with b_att in k_init/k_lstm)
        k_wgemm<<<dim3(A / 128, 16), 256>>>(hbuf, H, H / 32, wdecT, H,
                                            nullptr, 0, 0, nullptr, 0,
                                            dec, A, 16);
        k_attn<<<B, 512>>>(vatt, enc, t);
        // gates += xcat@W_ih^T + h@W_hh^T  (split-K=16; zeroed in k_attn)
        k_wgemm<<<dim3(G4 / 128, 16), 256>>>(xcat, HE, HE / 32, Wih, HE,
                                             hbuf, H,  H / 32,  Whh, H,
                                             gates, G4, 16);
        k_lstm<<<(B * H) / 256, 256>>>(batt, t);
    }
    // split hist to bf16 hi/lo, then mma.sync 3-term final GEMM
    k_cvt<<<(T * B * HE) / 512, 256>>>(hist, hH, hL);
    k_mout<<<dim3(V / 128, (T * B) / 128), 256>>>(hH, hL, wH, wL, bout, out);
}

// round 9
// speedup vs baseline: 2.9283x; 1.0211x over previous
#include <cuda_runtime.h>
#include <cstdint>

#define B 64
#define S 128
#define E 512
#define H 512
#define A 256
#define V 8192
#define T 32
#define HE 1024   /* H + E */
#define G4 2048   /* 4*H   */
#define KX 1536   /* H + E + H : gates GEMM K */

typedef unsigned long long ull;

// ---------------- persistent device scratch (no allocations allowed) -------
__device__ float g_enc_proj[B * S * A];   // 8 MB
__device__ float g_xemb[T * B * H];       // 4 MB
__device__ float g_hist[T * B * HE];      // 8 MB  [t*B+b][ h | ctx ]
__device__ __align__(16) unsigned short g_histH[T * B * HE];
__device__ __align__(16) unsigned short g_histL[T * B * HE];
__device__ __align__(16) unsigned short g_WoutH[V * HE];
__device__ __align__(16) unsigned short g_WoutL[V * HE];
__device__ __align__(16) unsigned short g_encH[B * S * E];
__device__ __align__(16) unsigned short g_encL[B * S * E];
__device__ __align__(16) unsigned short g_WencH[A * E];   // [A][E] (n-major)
__device__ __align__(16) unsigned short g_WencL[A * E];
__device__ __align__(16) unsigned short g_WgH[G4 * KX];   // [n][ Wih | Whh ]
__device__ __align__(16) unsigned short g_WgL[G4 * KX];
__device__ __align__(16) unsigned short g_xhH[B * KX];    // [b][ xemb | ctx | h ]
__device__ __align__(16) unsigned short g_xhL[B * KX];
__device__ float g_dec[B * A];
__device__ float g_c[B * H];
__device__ float g_gates[B * G4];
__device__ float g_bias[G4];              // b_ih + b_hh

// ---------------- helpers --------------------------------------------------
__device__ __forceinline__ float fast_tanh(float x) {
    float r; asm("tanh.approx.f32 %0, %1;" : "=f"(r) : "f"(x)); return r;
}
// pack (x0,x1) -> bf16x2 hi, residuals -> bf16x2 lo
__device__ __forceinline__ unsigned packhl(float x0, float x1, unsigned& lo_out) {
    unsigned hi;
    asm("cvt.rn.bf16x2.f32 %0, %1, %2;" : "=r"(hi) : "f"(x1), "f"(x0));
    float h0 = __uint_as_float(hi << 16);
    float h1 = __uint_as_float(hi & 0xffff0000u);
    float l0 = x0 - h0, l1 = x1 - h1;
    asm("cvt.rn.bf16x2.f32 %0, %1, %2;" : "=r"(lo_out) : "f"(l1), "f"(l0));
    return hi;
}
__device__ __forceinline__ void mma16816(float* c, uint32_t a0, uint32_t a1,
                                         uint32_t a2, uint32_t a3,
                                         uint32_t b0, uint32_t b1) {
    asm volatile(
        "mma.sync.aligned.m16n8k16.row.col.f32.bf16.bf16.f32 "
        "{%0,%1,%2,%3}, {%4,%5,%6,%7}, {%8,%9}, {%0,%1,%2,%3};"
        : "+f"(c[0]), "+f"(c[1]), "+f"(c[2]), "+f"(c[3])
        : "r"(a0), "r"(a1), "r"(a2), "r"(a3), "r"(b0), "r"(b1));
}

// ---------------- init: c=0, fused bias, seed dec, zero xh h-part ----------
__global__ void k_init(const float* __restrict__ b_ih, const float* __restrict__ b_hh,
                       const float* __restrict__ b_att) {
    int idx = blockIdx.x * 256 + threadIdx.x;   // 32768 threads
    if (idx < B * H) g_c[idx] = 0.f;
    if (idx < G4) g_bias[idx] = b_ih[idx] + b_hh[idx];
    if (idx < B * A) g_dec[idx] = b_att[idx & (A - 1)];
    {   // zero h-part of xh (h0 = 0): all 32768 = B*512
        int b = idx >> 9, j = idx & 511;
        g_xhH[b * KX + 1024 + j] = 0;
        g_xhL[b * KX + 1024 + j] = 0;
    }
}

// ---------------- gather teacher-forced embeddings for ALL steps -----------
__global__ void k_embed(const int* __restrict__ tgt, const float* __restrict__ emb) {
    int idx = blockIdx.x * 256 + threadIdx.x;   // T*B*H = 1M
    int hh = idx & (H - 1);
    int rb = idx >> 9;
    int b  = rb & (B - 1);
    int t  = rb >> 6;
    int tok = (t == 0) ? 0 : tgt[b * T + (t - 1)];
    g_xemb[idx] = emb[tok * H + hh];
}

// ---------------- fp32 -> (hi, lo) bf16 split, 2 elems/thread --------------
__global__ void k_cvt(const float* __restrict__ src,
                      unsigned short* __restrict__ dh,
                      unsigned short* __restrict__ dl) {
    int i = (blockIdx.x * 256 + threadIdx.x) * 2;
    float2 f = *(const float2*)&src[i];
    unsigned lo, hi = packhl(f.x, f.y, lo);
    *(unsigned*)&dh[i] = hi;
    *(unsigned*)&dl[i] = lo;
}

// ---------------- Wenc[E,A] -> WencT[A,E] hi/lo bf16 -----------------------
__global__ void k_tcvt(const float* __restrict__ Wenc) {
    int i = (blockIdx.x * 256 + threadIdx.x) * 2;   // over A*E
    int a = i >> 9, k = i & 511;
    float x0 = Wenc[k * A + a];
    float x1 = Wenc[(k + 1) * A + a];
    unsigned lo, hi = packhl(x0, x1, lo);
    *(unsigned*)&g_WencH[i] = hi;
    *(unsigned*)&g_WencL[i] = lo;
}

// ---------------- pack [Wih | Whh] -> Wg hi/lo bf16 ------------------------
__global__ void k_wgpack(const float* __restrict__ Wih, const float* __restrict__ Whh) {
    int i = (blockIdx.x * 256 + threadIdx.x) * 2;   // over G4*KX
    int n = i / KX, k = i % KX;
    float x0 = (k < HE) ? Wih[n * HE + k] : Whh[n * H + (k - HE)];
    float x1 = (k + 1 < HE) ? Wih[n * HE + k + 1] : Whh[n * H + (k + 1 - HE)];
    unsigned lo, hi = packhl(x0, x1, lo);
    *(unsigned*)&g_WgH[i] = hi;
    *(unsigned*)&g_WgL[i] = lo;
}

// ---------------- per-step FUSED: scores + softmax + ctx + xh pack ---------
// grid B, 512 threads.
__global__ void __launch_bounds__(512) k_attn(const float* __restrict__ v_att,
                                              const float* __restrict__ enc, int step) {
    __shared__ float sh_dec[A];
    __shared__ float sh_v[A];
    __shared__ float sw[S];
    __shared__ float sred;
    int b = blockIdx.x, tid = threadIdx.x;
    if (tid < A) { sh_dec[tid] = g_dec[b * A + tid]; sh_v[tid] = v_att[tid]; }
    // zero gates for split-K atomics (512 thr x 4 = G4 exactly)
    *(float4*)&g_gates[b * G4 + tid * 4] = make_float4(0.f, 0.f, 0.f, 0.f);
    // xemb -> xh[:512] hi/lo bf16
    {
        float xe = g_xemb[(step * B + b) * H + tid];
        float xep = __shfl_xor_sync(0xffffffffu, xe, 1);
        if (!(tid & 1)) {
            unsigned lo, hi = packhl(xe, xep, lo);
            *(unsigned*)&g_xhH[b * KX + tid] = hi;
            *(unsigned*)&g_xhL[b * KX + tid] = lo;
        }
    }
    __syncthreads();

    int wid = tid >> 5, lane = tid & 31;
#pragma unroll
    for (int r = 0; r < 8; r++) {             // 16 warps x 8 = 128 s-rows
        int s = wid * 8 + r;
        const float* ep = &g_enc_proj[(b * S + s) * A];
        float p = 0.f;
#pragma unroll
        for (int q = 0; q < 8; q++) {
            int a = lane + 32 * q;
            p += fast_tanh(ep[a] + sh_dec[a]) * sh_v[a];
        }
#pragma unroll
        for (int off = 16; off; off >>= 1) p += __shfl_down_sync(0xffffffffu, p, off);
        if (lane == 0) sw[s] = p;
    }
    __syncthreads();
    if (tid < 32) {
        float m = fmaxf(fmaxf(sw[tid], sw[tid + 32]), fmaxf(sw[tid + 64], sw[tid + 96]));
#pragma unroll
        for (int off = 16; off; off >>= 1) m = fmaxf(m, __shfl_xor_sync(0xffffffffu, m, off));
        if (tid == 0) sred = m;
    }
    __syncthreads();
    float mx = sred;
    if (tid < S) sw[tid] = expf(sw[tid] - mx);
    __syncthreads();
    if (tid < 32) {
        float ssum = sw[tid] + sw[tid + 32] + sw[tid + 64] + sw[tid + 96];
#pragma unroll
        for (int off = 16; off; off >>= 1) ssum += __shfl_xor_sync(0xffffffffu, ssum, off);
        if (tid == 0) sred = 1.f / ssum;
    }
    __syncthreads();
    float rinv = sred;

    // ctx[e]: one e per thread (512), coalesced over s
    float acc = 0.f;
    const float* eb = &enc[b * S * E + tid];
#pragma unroll 8
    for (int s = 0; s < S; s++)
        acc += sw[s] * eb[s * E];
    float v = acc * rinv;
    g_hist[(step * B + b) * HE + H + tid] = v;
    // ctx -> xh[512:1024] hi/lo
    float vp = __shfl_xor_sync(0xffffffffu, v, 1);
    if (!(tid & 1)) {
        unsigned lo, hi = packhl(v, vp, lo);
        *(unsigned*)&g_xhH[b * KX + 512 + tid] = hi;
        *(unsigned*)&g_xhL[b * KX + 512 + tid] = lo;
    }
}

// ---------------- gates GEMM: mma.sync bf16 3-term, M=64, split-K=8 --------
// gates[b][n] += sum_k xh[b][k] * Wg[n][k];  grid (16, 8), 256 thr.
#define PADK 40
__global__ void __launch_bounds__(256) k_mg() {
    __shared__ __align__(16) unsigned short sAh[64 * PADK], sAl[64 * PADK];
    __shared__ __align__(16) unsigned short sBh[128 * PADK], sBl[128 * PADK];
    int tid = threadIdx.x, warp = tid >> 5, lane = tid & 31;
    int N0 = blockIdx.x * 128;
    int wr = warp >> 2, wc = warp & 3;       // warp: 32m x 32n
    float acc[2][4][4];
#pragma unroll
    for (int i = 0; i < 2; i++)
#pragma unroll
        for (int j = 0; j < 4; j++)
#pragma unroll
            for (int q = 0; q < 4; q++) acc[i][j][q] = 0.f;

    int cr = tid >> 1, ch = (tid & 1) * 16;
    for (int kc = blockIdx.y; kc < KX / 32; kc += 8) {
        int k0 = kc * 32;
        if (tid < 128) {   // A: 64 rows
            const uint4* pa = (const uint4*)&g_xhH[cr * KX + k0 + ch];
            const uint4* pl = (const uint4*)&g_xhL[cr * KX + k0 + ch];
            uint4* da = (uint4*)&sAh[cr * PADK + ch];
            uint4* dl = (uint4*)&sAl[cr * PADK + ch];
            da[0] = pa[0]; da[1] = pa[1];
            dl[0] = pl[0]; dl[1] = pl[1];
        }
        {   // B: 128 rows
            const uint4* pb = (const uint4*)&g_WgH[(size_t)(N0 + cr) * KX + k0 + ch];
            const uint4* pbl= (const uint4*)&g_WgL[(size_t)(N0 + cr) * KX + k0 + ch];
            uint4* db = (uint4*)&sBh[cr * PADK + ch];
            uint4* dbl= (uint4*)&sBl[cr * PADK + ch];
            db[0] = pb[0]; db[1] = pb[1];
            dbl[0]= pbl[0]; dbl[1]= pbl[1];
        }
        __syncthreads();
#pragma unroll
        for (int kq = 0; kq < 2; kq++) {
            int kb = kq * 16 + (lane & 3) * 2;
            uint32_t ah[2][4], al[2][4], bh[4][2], bl[4][2];
#pragma unroll
            for (int mf = 0; mf < 2; mf++) {
                int r = wr * 32 + mf * 16 + (lane >> 2);
                ah[mf][0] = *(const uint32_t*)&sAh[r * PADK + kb];
                ah[mf][1] = *(const uint32_t*)&sAh[(r + 8) * PADK + kb];
                ah[mf][2] = *(const uint32_t*)&sAh[r * PADK + kb + 8];
                ah[mf][3] = *(const uint32_t*)&sAh[(r + 8) * PADK + kb + 8];
                al[mf][0] = *(const uint32_t*)&sAl[r * PADK + kb];
                al[mf][1] = *(const uint32_t*)&sAl[(r + 8) * PADK + kb];
                al[mf][2] = *(const uint32_t*)&sAl[r * PADK + kb + 8];
                al[mf][3] = *(const uint32_t*)&sAl[(r + 8) * PADK + kb + 8];
            }
#pragma unroll
            for (int nf = 0; nf < 4; nf++) {
                int r = wc * 32 + nf * 8 + (lane >> 2);
                bh[nf][0] = *(const uint32_t*)&sBh[r * PADK + kb];
                bh[nf][1] = *(const uint32_t*)&sBh[r * PADK + kb + 8];
                bl[nf][0] = *(const uint32_t*)&sBl[r * PADK + kb];
                bl[nf][1] = *(const uint32_t*)&sBl[r * PADK + kb + 8];
            }
#pragma unroll
            for (int mf = 0; mf < 2; mf++)
#pragma unroll
                for (int nf = 0; nf < 4; nf++) {
                    mma16816(acc[mf][nf], ah[mf][0], ah[mf][1], ah[mf][2], ah[mf][3],
                             bh[nf][0], bh[nf][1]);
                    mma16816(acc[mf][nf], al[mf][0], al[mf][1], al[mf][2], al[mf][3],
                             bh[nf][0], bh[nf][1]);
                    mma16816(acc[mf][nf], ah[mf][0], ah[mf][1], ah[mf][2], ah[mf][3],
                             bl[nf][0], bl[nf][1]);
                }
        }
        __syncthreads();
    }
#pragma unroll
    for (int mf = 0; mf < 2; mf++) {
        int m = wr * 32 + mf * 16 + (lane >> 2);
#pragma unroll
        for (int nf = 0; nf < 4; nf++) {
            int n = N0 + wc * 32 + nf * 8 + (lane & 3) * 2;
            atomicAdd(&g_gates[m * G4 + n],           acc[mf][nf][0]);
            atomicAdd(&g_gates[m * G4 + n + 1],       acc[mf][nf][1]);
            atomicAdd(&g_gates[(m + 8) * G4 + n],     acc[mf][nf][2]);
            atomicAdd(&g_gates[(m + 8) * G4 + n + 1], acc[mf][nf][3]);
        }
    }
}

// ---------------- per-step FUSED: LSTM cell + h pack + dec projection ------
// grid B, 512 threads.
__global__ void __launch_bounds__(512) k_lstm2(const float* __restrict__ b_att,
                                               const float* __restrict__ Wdec, int step) {
    __shared__ float sh[H];
    __shared__ float sred[512];
    int b = blockIdx.x, tid = threadIdx.x;
    const float* gr = &g_gates[b * G4];
    float gi = gr[tid]         + g_bias[tid];
    float gf = gr[tid + 512]   + g_bias[tid + 512];
    float gg = gr[tid + 1024]  + g_bias[tid + 1024];
    float go = gr[tid + 1536]  + g_bias[tid + 1536];
    float si = 1.f / (1.f + expf(-gi));
    float sf = 1.f / (1.f + expf(-gf));
    float so = 1.f / (1.f + expf(-go));
    float c  = sf * g_c[b * H + tid] + si * tanhf(gg);
    float hn = so * tanhf(c);
    g_c[b * H + tid] = c;
    g_hist[(step * B + b) * HE + tid] = hn;
    sh[tid] = hn;
    // h -> xh[1024:1536] hi/lo (for next step's gates GEMM)
    float hp = __shfl_xor_sync(0xffffffffu, hn, 1);
    if (!(tid & 1)) {
        unsigned lo, hi = packhl(hn, hp, lo);
        *(unsigned*)&g_xhH[b * KX + 1024 + tid] = hi;
        *(unsigned*)&g_xhL[b * KX + 1024 + tid] = lo;
    }
    __syncthreads();
    // dec[b][a] = h . Wdec[:,a] + b_att[a]  (2 threads per a, k-halves)
    int a = tid & 255, kh = tid >> 8;
    float acc = 0.f;
    const float* wp = &Wdec[(kh * 256) * A + a];
#pragma unroll 8
    for (int k = 0; k < 256; k++)
        acc += sh[kh * 256 + k] * wp[k * A];
    sred[tid] = acc;
    __syncthreads();
    if (tid < 256)
        g_dec[b * A + tid] = sred[tid] + sred[tid + 256] + b_att[tid];
}

// ---------------- generic 128x128 mma.sync bf16 3-term GEMM ----------------
// out[row(m)][N0+n] = sum_k A[m][k]*Bw[n][k] (+bias); perm: m -> (m&63)*T+(m>>6)
__global__ void __launch_bounds__(256) k_mma128(
    const unsigned short* __restrict__ Ahg, const unsigned short* __restrict__ Alg,
    const unsigned short* __restrict__ Bhg, const unsigned short* __restrict__ Blg,
    int ldk, int nkc, const float* __restrict__ bias,
    float* __restrict__ out, int ldc, int perm)
{
    __shared__ __align__(16) unsigned short sAh[128 * PADK], sAl[128 * PADK];
    __shared__ __align__(16) unsigned short sBh[128 * PADK], sBl[128 * PADK];
    int tid = threadIdx.x, warp = tid >> 5, lane = tid & 31;
    int N0 = blockIdx.x * 128, M0 = blockIdx.y * 128;
    int wr = warp >> 2, wc = warp & 3;
    float acc[4][4][4];
#pragma unroll
    for (int i = 0; i < 4; i++)
#pragma unroll
        for (int j = 0; j < 4; j++)
#pragma unroll
            for (int q = 0; q < 4; q++) acc[i][j][q] = 0.f;

    int cr = tid >> 1, ch = (tid & 1) * 16;
    for (int kc = 0; kc < nkc; kc++) {
        int k0 = kc * 32;
        {
            const uint4* pa = (const uint4*)&Ahg[(size_t)(M0 + cr) * ldk + k0 + ch];
            const uint4* pl = (const uint4*)&Alg[(size_t)(M0 + cr) * ldk + k0 + ch];
            const uint4* pb = (const uint4*)&Bhg[(size_t)(N0 + cr) * ldk + k0 + ch];
            const uint4* pbl= (const uint4*)&Blg[(size_t)(N0 + cr) * ldk + k0 + ch];
            uint4* da = (uint4*)&sAh[cr * PADK + ch];
            uint4* dl = (uint4*)&sAl[cr * PADK + ch];
            uint4* db = (uint4*)&sBh[cr * PADK + ch];
            uint4* dbl= (uint4*)&sBl[cr * PADK + ch];
            da[0] = pa[0]; da[1] = pa[1];
            dl[0] = pl[0]; dl[1] = pl[1];
            db[0] = pb[0]; db[1] = pb[1];
            dbl[0]= pbl[0]; dbl[1]= pbl[1];
        }
        __syncthreads();
#pragma unroll
        for (int kq = 0; kq < 2; kq++) {
            int kb = kq * 16 + (lane & 3) * 2;
            uint32_t ah[4][4], al[4][4], bh[4][2], bl[4][2];
            int ar = wr * 64 + (lane >> 2);
#pragma unroll
            for (int mf = 0; mf < 4; mf++) {
                int r = ar + mf * 16;
                ah[mf][0] = *(const uint32_t*)&sAh[r * PADK + kb];
                ah[mf][1] = *(const uint32_t*)&sAh[(r + 8) * PADK + kb];
                ah[mf][2] = *(const uint32_t*)&sAh[r * PADK + kb + 8];
                ah[mf][3] = *(const uint32_t*)&sAh[(r + 8) * PADK + kb + 8];
                al[mf][0] = *(const uint32_t*)&sAl[r * PADK + kb];
                al[mf][1] = *(const uint32_t*)&sAl[(r + 8) * PADK + kb];
                al[mf][2] = *(const uint32_t*)&sAl[r * PADK + kb + 8];
                al[mf][3] = *(const uint32_t*)&sAl[(r + 8) * PADK + kb + 8];
            }
            int br = wc * 32 + (lane >> 2);
#pragma unroll
            for (int nf = 0; nf < 4; nf++) {
                int r = br + nf * 8;
                bh[nf][0] = *(const uint32_t*)&sBh[r * PADK + kb];
                bh[nf][1] = *(const uint32_t*)&sBh[r * PADK + kb + 8];
                bl[nf][0] = *(const uint32_t*)&sBl[r * PADK + kb];
                bl[nf][1] = *(const uint32_t*)&sBl[r * PADK + kb + 8];
            }
#pragma unroll
            for (int mf = 0; mf < 4; mf++)
#pragma unroll
                for (int nf = 0; nf < 4; nf++) {
                    mma16816(acc[mf][nf], ah[mf][0], ah[mf][1], ah[mf][2], ah[mf][3],
                             bh[nf][0], bh[nf][1]);
                    mma16816(acc[mf][nf], al[mf][0], al[mf][1], al[mf][2], al[mf][3],
                             bh[nf][0], bh[nf][1]);
                    mma16816(acc[mf][nf], ah[mf][0], ah[mf][1], ah[mf][2], ah[mf][3],
                             bl[nf][0], bl[nf][1]);
                }
        }
        __syncthreads();
    }
#pragma unroll
    for (int mf = 0; mf < 4; mf++) {
        int m0g = M0 + wr * 64 + mf * 16 + (lane >> 2);
#pragma unroll
        for (int nf = 0; nf < 4; nf++) {
            int n = N0 + wc * 32 + nf * 8 + (lane & 3) * 2;
            float2 bia = bias ? *(const float2*)&bias[n] : make_float2(0.f, 0.f);
            int m1 = m0g + 8;
            int r0 = perm ? ((m0g & 63) * T + (m0g >> 6)) : m0g;
            int r1 = perm ? ((m1 & 63) * T + (m1 >> 6)) : m1;
            float2 v0 = make_float2(acc[mf][nf][0] + bia.x, acc[mf][nf][1] + bia.y);
            float2 v1 = make_float2(acc[mf][nf][2] + bia.x, acc[mf][nf][3] + bia.y);
            *(float2*)&out[(size_t)r0 * ldc + n] = v0;
            *(float2*)&out[(size_t)r1 * ldc + n] = v1;
        }
    }
}

// ---------------- launch ----------------------------------------------------
extern "C" void kernel_launch(void* const* d_in, const int* in_sizes, int n_in,
                              void* d_out, int out_size) {
    const float* enc  = (const float*)d_in[0];
    const int*   tgt  = (const int*)  d_in[1];
    const float* emb  = (const float*)d_in[2];
    const float* Wenc = (const float*)d_in[3];
    const float* Wdec = (const float*)d_in[4];
    const float* batt = (const float*)d_in[5];
    const float* vatt = (const float*)d_in[6];
    const float* Wih  = (const float*)d_in[7];
    const float* Whh  = (const float*)d_in[8];
    const float* bih  = (const float*)d_in[9];
    const float* bhh  = (const float*)d_in[10];
    const float* Wout = (const float*)d_in[11];
    const float* bout = (const float*)d_in[12];
    float* out = (float*)d_out;

    float *encp, *hist;
    unsigned short *hH, *hL, *wH, *wL, *eH, *eL, *weH, *weL;
    cudaGetSymbolAddress((void**)&encp,  g_enc_proj);
    cudaGetSymbolAddress((void**)&hist,  g_hist);
    cudaGetSymbolAddress((void**)&hH, g_histH);
    cudaGetSymbolAddress((void**)&hL, g_histL);
    cudaGetSymbolAddress((void**)&wH, g_WoutH);
    cudaGetSymbolAddress((void**)&wL, g_WoutL);
    cudaGetSymbolAddress((void**)&eH, g_encH);
    cudaGetSymbolAddress((void**)&eL, g_encL);
    cudaGetSymbolAddress((void**)&weH, g_WencH);
    cudaGetSymbolAddress((void**)&weL, g_WencL);

    k_init<<<128, 256>>>(bih, bhh, batt);
    k_embed<<<(T * B * H) / 256, 256>>>(tgt, emb);
    k_cvt<<<(B * S * E) / 512, 256>>>(enc, eH, eL);
    k_tcvt<<<(A * E) / 512, 256>>>(Wenc);
    k_wgpack<<<(G4 * KX) / 512, 256>>>(Wih, Whh);
    k_cvt<<<(V * HE) / 512, 256>>>(Wout, wH, wL);
    // enc_proj[8192,256] = enc @ WencT^T  (mma, no bias, no permute)
    k_mma128<<<dim3(A / 128, (B * S) / 128), 256>>>(eH, eL, weH, weL,
                                                    E, E / 32, nullptr, encp, A, 0);

    for (int t = 0; t < T; t++) {
        k_attn<<<B, 512>>>(vatt, enc, t);
        k_mg<<<dim3(G4 / 128, 8), 256>>>();
        k_lstm2<<<B, 512>>>(batt, Wdec, t);
    }
    // final: hist -> hi/lo, then out = hist @ Wout^T + bout (permuted store)
    k_cvt<<<(T * B * HE) / 512, 256>>>(hist, hH, hL);
    k_mma128<<<dim3(V / 128, (T * B) / 128), 256>>>(hH, hL, wH, wL,
                                                    HE, HE / 32, bout, out, V, 1);
}